// round 1
// baseline (speedup 1.0000x reference)
#include <cuda_runtime.h>

#define D   128
#define KN  32
#define NV_MAX  200000
#define NN_MAX  20000

// Scratch (allocation-free per harness rules)
__device__ float g_P[(size_t)NV_MAX * D];   // video_embeddings @ W1a   (102.4 MB)
__device__ float g_Q[(size_t)NN_MAX * D];   // V[nodes] @ W1b + b1     (10.2 MB)

typedef unsigned long long u64;

__device__ __forceinline__ u64 pack2(float x, float y) {
    u64 r; asm("mov.b64 %0, {%1, %2};" : "=l"(r) : "f"(x), "f"(y)); return r;
}
__device__ __forceinline__ void unpack2(u64 v, float &x, float &y) {
    asm("mov.b64 {%0, %1}, %2;" : "=f"(x), "=f"(y) : "l"(v));
}
// packed fp32x2 FMA: acc.{lo,hi} += a.{lo,hi} * b.{lo,hi}  (2x FFMA rate on sm_103a)
__device__ __forceinline__ void fma2(u64 &acc, u64 a, u64 b) {
    asm("fma.rn.f32x2 %0, %1, %2, %0;" : "+l"(acc) : "l"(a), "l"(b));
}

// ---------------------------------------------------------------------------
// proj_kernel: out[r][d] = sum_e src_row[r][e] * W[e][d]  (+ bias[d] if BIAS)
// 8 rows per block, 128 threads (thread = output column d).
// Rows are packed pairwise into f32x2 accumulators.
// GATHER: rows come from an index array (video_nodes), dest = g_Q.
// ---------------------------------------------------------------------------
template<bool GATHER>
__global__ void __launch_bounds__(128) proj_kernel(
    const float* __restrict__ V, const float* __restrict__ W,
    const float* __restrict__ bias, const int* __restrict__ rows, int n_rows)
{
    __shared__ float vsh[D][8];           // [e][r], 4 KB
    const int t = threadIdx.x;            // column d / load lane
    const int row0 = blockIdx.x * 8;

    #pragma unroll
    for (int r = 0; r < 8; r++) {
        int row = row0 + r;
        if (row >= n_rows) row = n_rows - 1;       // clamp (grids divide exactly anyway)
        int src = GATHER ? rows[row] : row;
        vsh[t][r] = V[(size_t)src * D + t];
    }
    __syncthreads();

    u64 acc[4] = {0ull, 0ull, 0ull, 0ull};
    #pragma unroll 4
    for (int e = 0; e < D; e++) {
        float w = W[e * D + t];
        u64 wp = pack2(w, w);
        ulonglong2 p0 = *(const ulonglong2*)&vsh[e][0];   // rows (0,1),(2,3)
        ulonglong2 p1 = *(const ulonglong2*)&vsh[e][4];   // rows (4,5),(6,7)
        fma2(acc[0], p0.x, wp);
        fma2(acc[1], p0.y, wp);
        fma2(acc[2], p1.x, wp);
        fma2(acc[3], p1.y, wp);
    }

    float bb = GATHER ? bias[t] : 0.0f;
    float* dst = GATHER ? g_Q : g_P;
    #pragma unroll
    for (int rp = 0; rp < 4; rp++) {
        float x, y; unpack2(acc[rp], x, y);
        int r0 = row0 + 2 * rp, r1 = r0 + 1;
        if (r0 < n_rows) dst[(size_t)r0 * D + t] = x + bb;
        if (r1 < n_rows) dst[(size_t)r1 * D + t] = y + bb;
    }
}

// ---------------------------------------------------------------------------
// agg_kernel: one block (128 threads) per node.
//   h1[k][e] = relu(P[neigh[k]][e] + Q[n][e])           (elementwise, no GEMM)
//   h2[k][d] = relu(sum_e h1[k][e]*W2[e][d] + b2[d])    (f32x2, k paired)
//   s[k]     = sum_d h2[k][d]*W3[d]                     (block reduce)
//   att      = softmax(s);  out[n][d] = sum_k att[k]*V[neigh[k]][d]
// ---------------------------------------------------------------------------
__global__ void __launch_bounds__(128) agg_kernel(
    const float* __restrict__ V, const int* __restrict__ neigh,
    const float* __restrict__ W2, const float* __restrict__ b2,
    const float* __restrict__ W3, float* __restrict__ out)
{
    // sbuf serves two phases:
    //   phase 1: h1 pairs,  layout [e][kp], row stride 36 floats (18 float2) -> 16B aligned
    //   phase 2: score scratch scr[k][t], row stride 132 floats (pad kills bank conflicts)
    __shared__ float sbuf[D * 36];        // 18 KB (>= 32*132*4 = 16.9 KB)
    __shared__ float nv[KN * D];          // neighbor embeddings, 16 KB
    __shared__ int   idx[KN];
    __shared__ float s_att[KN];

    const int t = threadIdx.x;            // 0..127
    const int n = blockIdx.x;

    if (t < KN) idx[t] = neigh[n * KN + t];
    __syncthreads();

    // ---- phase 1: build h1 (paired over k) + gather neighbor embeddings ----
    const float qd = g_Q[(size_t)n * D + t];
    #pragma unroll
    for (int kp = 0; kp < KN / 2; kp++) {
        float p0 = g_P[(size_t)idx[2 * kp]     * D + t];
        float p1 = g_P[(size_t)idx[2 * kp + 1] * D + t];
        float h0 = fmaxf(p0 + qd, 0.0f);
        float h1 = fmaxf(p1 + qd, 0.0f);
        *(float2*)&sbuf[t * 36 + kp * 2] = make_float2(h0, h1);
    }
    #pragma unroll
    for (int k = 0; k < KN; k++)
        nv[k * D + t] = V[(size_t)idx[k] * D + t];
    __syncthreads();

    // ---- phase 2: h2 GEMM, thread = column d, f32x2 over neighbor pairs ----
    u64 acc[16];
    #pragma unroll
    for (int i = 0; i < 16; i++) acc[i] = 0ull;

    #pragma unroll 2
    for (int e = 0; e < D; e++) {
        float w = W2[e * D + t];
        u64 wp = pack2(w, w);
        const ulonglong2* hp = (const ulonglong2*)&sbuf[e * 36];
        #pragma unroll
        for (int q = 0; q < 8; q++) {
            ulonglong2 pr = hp[q];                  // kp = 2q, 2q+1 (broadcast LDS)
            fma2(acc[2 * q],     pr.x, wp);
            fma2(acc[2 * q + 1], pr.y, wp);
        }
    }

    // ---- scores: c[k] = relu(acc + b2[d]) * W3[d], then block-reduce over d ----
    const float b2d = b2[t];
    const float w3d = W3[t];
    float c[KN];
    #pragma unroll
    for (int kp = 0; kp < 16; kp++) {
        float x, y; unpack2(acc[kp], x, y);
        c[2 * kp]     = fmaxf(x + b2d, 0.0f) * w3d;
        c[2 * kp + 1] = fmaxf(y + b2d, 0.0f) * w3d;
    }
    __syncthreads();                       // everyone done reading sbuf as h1
    #pragma unroll
    for (int k = 0; k < KN; k++) sbuf[k * 132 + t] = c[k];
    __syncthreads();

    const int lane = t & 31, wrp = t >> 5;
    #pragma unroll
    for (int j = 0; j < 8; j++) {
        int k = wrp * 8 + j;
        const float* p = &sbuf[k * 132];
        float v = (p[lane] + p[lane + 32]) + (p[lane + 64] + p[lane + 96]);
        #pragma unroll
        for (int o = 16; o > 0; o >>= 1) v += __shfl_xor_sync(0xffffffffu, v, o);
        if (lane == 0) s_att[k] = v;
    }
    __syncthreads();

    // ---- softmax over 32 (warp 0) ----
    if (t < 32) {
        float v = s_att[t];
        float m = v;
        #pragma unroll
        for (int o = 16; o > 0; o >>= 1) m = fmaxf(m, __shfl_xor_sync(0xffffffffu, m, o));
        float ev = expf(v - m);
        float sum = ev;
        #pragma unroll
        for (int o = 16; o > 0; o >>= 1) sum += __shfl_xor_sync(0xffffffffu, sum, o);
        s_att[t] = ev / sum;
    }
    __syncthreads();

    // ---- weighted aggregation ----
    float o = 0.0f;
    #pragma unroll
    for (int k = 0; k < KN; k++) o = fmaf(s_att[k], nv[k * D + t], o);
    out[(size_t)n * D + t] = o;
}

// ---------------------------------------------------------------------------
extern "C" void kernel_launch(void* const* d_in, const int* in_sizes, int n_in,
                              void* d_out, int out_size)
{
    const float* V     = (const float*)d_in[0];   // [200000,128]
    const int*   nodes = (const int*)  d_in[1];   // [20000]
    const int*   neigh = (const int*)  d_in[2];   // [20000,32]
    const float* W1    = (const float*)d_in[3];   // [256,128]
    const float* b1    = (const float*)d_in[4];   // [128]
    const float* W2    = (const float*)d_in[5];   // [128,128]
    const float* b2    = (const float*)d_in[6];   // [128]
    const float* W3    = (const float*)d_in[7];   // [128,1]
    // d_in[8] = b3: constant shift, softmax-invariant -> dropped
    float* out = (float*)d_out;

    const int n_videos = in_sizes[0] / D;         // 200000
    const int n_nodes  = in_sizes[1];              // 20000

    // P = V @ W1[:128]           (all videos)
    proj_kernel<false><<<(n_videos + 7) / 8, 128>>>(V, W1, nullptr, nullptr, n_videos);
    // Q = V[nodes] @ W1[128:] + b1
    proj_kernel<true ><<<(n_nodes  + 7) / 8, 128>>>(V, W1 + D * D, b1, nodes, n_nodes);
    // per-node attention + aggregation
    agg_kernel<<<n_nodes, 128>>>(V, neigh, W2, b2, W3, out);
}

// round 3
// speedup vs baseline: 1.6321x; 1.6321x over previous
#include <cuda_runtime.h>
#include <cuda_bf16.h>
#include <cstdint>

#define D 128
#define NV_MAX 200000
#define NN_MAX 20000

typedef unsigned long long u64;
typedef unsigned int u32;

// ---------------- device scratch (no allocs allowed) ------------------------
__device__ float g_P[(size_t)NV_MAX * D];            // V @ W1a (fp32)
__device__ float g_Q[(size_t)NN_MAX * D];            // V[nodes] @ W1b + b1
// pre-swizzled bf16 weight images: [which][ hi 32KB | lo 32KB ]
__device__ __align__(16) unsigned char g_Bimg[2][65536];

// ---------------- smem layout (dynamic, 1KB aligned) ------------------------
#define A_OFF     0          // A_hi 16KB | A_lo 16KB
#define B_OFF     32768      // B_hi 32KB | B_lo 32KB
#define MISC_OFF  98304
#define IDX_OFF   (MISC_OFF)          // 64 int
#define BW_OFF    (MISC_OFF + 256)    // float2[128]
#define SP_OFF    (MISC_OFF + 1280)   // float[2][64]
#define ATT_OFF   (MISC_OFF + 1792)   // float[64]
#define AGP_OFF   (MISC_OFF + 2048)   // float4[4][32]
#define SMEM_BYTES (MISC_OFF + 4096 + 1024)

// ---------------- helpers ----------------------------------------------------
__device__ __forceinline__ u32 smem_u32(const void* p) {
    u32 a; asm("{ .reg .u64 t; cvta.to.shared.u64 t, %1; cvt.u32.u64 %0, t; }" : "=r"(a) : "l"(p));
    return a;
}
__device__ __forceinline__ void ldm_x4(u32 addr, u32* r) {
    asm volatile("ldmatrix.sync.aligned.m8n8.x4.shared.b16 {%0,%1,%2,%3}, [%4];"
        : "=r"(r[0]), "=r"(r[1]), "=r"(r[2]), "=r"(r[3]) : "r"(addr));
}
__device__ __forceinline__ void mma_bf16(float* c, const u32* a, const u32* b) {
    asm volatile("mma.sync.aligned.m16n8k16.row.col.f32.bf16.bf16.f32 "
        "{%0,%1,%2,%3}, {%4,%5,%6,%7}, {%8,%9}, {%0,%1,%2,%3};"
        : "+f"(c[0]), "+f"(c[1]), "+f"(c[2]), "+f"(c[3])
        : "r"(a[0]), "r"(a[1]), "r"(a[2]), "r"(a[3]), "r"(b[0]), "r"(b[1]));
}
// pack float4 into bf16 hi (8B) + bf16 lo residual (8B), k-order preserved
__device__ __forceinline__ void split4(float4 v, uint2& hi, uint2& lo) {
    u32 h01, h23;
    asm("cvt.rn.bf16x2.f32 %0, %1, %2;" : "=r"(h01) : "f"(v.y), "f"(v.x));
    asm("cvt.rn.bf16x2.f32 %0, %1, %2;" : "=r"(h23) : "f"(v.w), "f"(v.z));
    float rx = v.x - __bfloat162float(__ushort_as_bfloat16((unsigned short)(h01 & 0xffff)));
    float ry = v.y - __bfloat162float(__ushort_as_bfloat16((unsigned short)(h01 >> 16)));
    float rz = v.z - __bfloat162float(__ushort_as_bfloat16((unsigned short)(h23 & 0xffff)));
    float rw = v.w - __bfloat162float(__ushort_as_bfloat16((unsigned short)(h23 >> 16)));
    u32 l01, l23;
    asm("cvt.rn.bf16x2.f32 %0, %1, %2;" : "=r"(l01) : "f"(ry), "f"(rx));
    asm("cvt.rn.bf16x2.f32 %0, %1, %2;" : "=r"(l23) : "f"(rw), "f"(rz));
    hi = make_uint2(h01, h23); lo = make_uint2(l01, l23);
}

// ---------------- shared GEMM: block tile 64x128, warp tile 32x64 ------------
// A: [64 rows][128 k] bf16, 256B rows, 16B chunks XOR-swizzled by (row&7).
// B: [128 n][128 k] bf16 (= W^T), same row format. 3-pass: AhBh + AlBh + AhBl.
__device__ __forceinline__ void gemm_tile(u32 sA, u32 sB, int lane, int mw, int nw,
                                          float acc[2][8][4]) {
    const int lr   = lane & 7;
    const int akl  = lane >> 4;                       // A k-half select
    const int arow = lr + ((lane >> 3) & 1) * 8;      // A row within 16
    const int bkl  = (lane >> 3) & 1;                 // B k-half select
    const int brow = lr + (lane >> 4) * 8;            // B row within 16
    u32 aoffm[2], boffn[4];
    #pragma unroll
    for (int mt = 0; mt < 2; mt++) aoffm[mt] = (u32)((32 * mw + 16 * mt + arow) * 256);
    #pragma unroll
    for (int n2 = 0; n2 < 4; n2++)  boffn[n2] = (u32)((64 * nw + 16 * n2 + brow) * 256);

    #pragma unroll 1
    for (int ks = 0; ks < 8; ks++) {
        const int kc0 = ks * 2;
        const u32 axor = (u32)(((kc0 + akl) ^ lr) << 4);
        const u32 bxor = (u32)(((kc0 + bkl) ^ lr) << 4);
        u32 ah[2][4], al[2][4], b[4][4];
        #pragma unroll
        for (int mt = 0; mt < 2; mt++) {
            ldm_x4(sA + aoffm[mt] + axor, ah[mt]);
            ldm_x4(sA + 16384 + aoffm[mt] + axor, al[mt]);
        }
        #pragma unroll
        for (int n2 = 0; n2 < 4; n2++) ldm_x4(sB + boffn[n2] + bxor, b[n2]);
        #pragma unroll
        for (int mt = 0; mt < 2; mt++)
            #pragma unroll
            for (int nt = 0; nt < 8; nt++) {
                mma_bf16(acc[mt][nt], ah[mt], &b[nt >> 1][(nt & 1) * 2]);
                mma_bf16(acc[mt][nt], al[mt], &b[nt >> 1][(nt & 1) * 2]);
            }
        #pragma unroll
        for (int n2 = 0; n2 < 4; n2++) ldm_x4(sB + 32768 + boffn[n2] + bxor, b[n2]);
        #pragma unroll
        for (int mt = 0; mt < 2; mt++)
            #pragma unroll
            for (int nt = 0; nt < 8; nt++)
                mma_bf16(acc[mt][nt], ah[mt], &b[nt >> 1][(nt & 1) * 2]);
    }
}

__device__ __forceinline__ void stage_B(char* smc, const unsigned char* img, int t) {
    const float4* src = (const float4*)img;
    float4* dst = (float4*)(smc + B_OFF);
    #pragma unroll
    for (int i = 0; i < 32; i++) dst[t + 128 * i] = src[t + 128 * i];
}

// ---------------- prep: W -> transposed, split, swizzled bf16 images ---------
__global__ void prep_kernel(const float* __restrict__ W1, const float* __restrict__ W2) {
    const float* W = blockIdx.x ? W2 : W1;     // W1: rows 0..127 = W1a
    unsigned char* img = g_Bimg[blockIdx.x];
    int n = threadIdx.x;
    for (int k = 0; k < D; k++) {
        float v = W[k * D + n];
        __nv_bfloat16 h = __float2bfloat16(v);
        float rem = v - __bfloat162float(h);
        __nv_bfloat16 l = __float2bfloat16(rem);
        int o = n * 256 + ((((k >> 3) ^ (n & 7))) << 4) + ((k & 7) << 1);
        *(__nv_bfloat16*)(img + o) = h;
        *(__nv_bfloat16*)(img + 32768 + o) = l;
    }
}

// ---------------- Q projection (SIMT f32x2, small) ---------------------------
__device__ __forceinline__ u64 pack2(float x, float y) {
    u64 r; asm("mov.b64 %0, {%1, %2};" : "=l"(r) : "f"(x), "f"(y)); return r;
}
__device__ __forceinline__ void unpack2(u64 v, float& x, float& y) {
    asm("mov.b64 {%0, %1}, %2;" : "=f"(x), "=f"(y) : "l"(v));
}
__device__ __forceinline__ void fma2(u64& acc, u64 a, u64 b) {
    asm("fma.rn.f32x2 %0, %1, %2, %0;" : "+l"(acc) : "l"(a), "l"(b));
}
__global__ void __launch_bounds__(128) qproj_kernel(
    const float* __restrict__ V, const float* __restrict__ W,
    const float* __restrict__ bias, const int* __restrict__ rows, int n_rows)
{
    __shared__ float vsh[D][8];
    const int t = threadIdx.x;
    const int row0 = blockIdx.x * 8;
    #pragma unroll
    for (int r = 0; r < 8; r++) {
        int row = row0 + r; if (row >= n_rows) row = n_rows - 1;
        vsh[t][r] = V[(size_t)rows[row] * D + t];
    }
    __syncthreads();
    u64 acc[4] = {0ull, 0ull, 0ull, 0ull};
    #pragma unroll 4
    for (int e = 0; e < D; e++) {
        float w = W[e * D + t];
        u64 wp = pack2(w, w);
        ulonglong2 p0 = *(const ulonglong2*)&vsh[e][0];
        ulonglong2 p1 = *(const ulonglong2*)&vsh[e][4];
        fma2(acc[0], p0.x, wp); fma2(acc[1], p0.y, wp);
        fma2(acc[2], p1.x, wp); fma2(acc[3], p1.y, wp);
    }
    float bb = bias[t];
    #pragma unroll
    for (int rp = 0; rp < 4; rp++) {
        float x, y; unpack2(acc[rp], x, y);
        int r0 = row0 + 2 * rp, r1 = r0 + 1;
        if (r0 < n_rows) g_Q[(size_t)r0 * D + t] = x + bb;
        if (r1 < n_rows) g_Q[(size_t)r1 * D + t] = y + bb;
    }
}

// ---------------- P projection: P = V @ W1a (persistent, HMMA) ---------------
__global__ void __launch_bounds__(128) pproj_kernel(const float* __restrict__ V,
                                                    int n_videos, int n_tiles)
{
    extern __shared__ char dsm[];
    char* smc = (char*)(((uintptr_t)dsm + 1023) & ~(uintptr_t)1023);
    u32 sb = smem_u32(smc);
    const int t = threadIdx.x, w = t >> 5, lane = t & 31;
    const int mw = w >> 1, nw = w & 1;

    stage_B(smc, g_Bimg[0], t);
    const float4* V4 = (const float4*)V;

    for (int tile = blockIdx.x; tile < n_tiles; tile += gridDim.x) {
        __syncthreads();
        const int r0g = tile * 64;
        #pragma unroll 4
        for (int i = 0; i < 16; i++) {
            int r = w * 16 + i;
            int gr = r0g + r; if (gr >= n_videos) gr = n_videos - 1;
            float4 v = V4[(size_t)gr * 32 + lane];
            uint2 hi, lo; split4(v, hi, lo);
            u32 byte = (u32)(r * 256 + ((((u32)(lane >> 1)) ^ (u32)(r & 7)) << 4) + ((lane & 1) << 3));
            *(uint2*)(smc + A_OFF + byte) = hi;
            *(uint2*)(smc + A_OFF + 16384 + byte) = lo;
        }
        __syncthreads();

        float acc[2][8][4];
        #pragma unroll
        for (int a = 0; a < 2; a++)
            #pragma unroll
            for (int b = 0; b < 8; b++)
                #pragma unroll
                for (int c = 0; c < 4; c++) acc[a][b][c] = 0.f;

        gemm_tile(sb + A_OFF, sb + B_OFF, lane, mw, nw, acc);

        #pragma unroll
        for (int mt = 0; mt < 2; mt++)
            #pragma unroll
            for (int nt = 0; nt < 8; nt++) {
                int gr = r0g + 32 * mw + 16 * mt + (lane >> 2);
                int gc = 64 * nw + 8 * nt + 2 * (lane & 3);
                if (gr < n_videos)
                    *(float2*)&g_P[(size_t)gr * D + gc] = make_float2(acc[mt][nt][0], acc[mt][nt][1]);
                if (gr + 8 < n_videos)
                    *(float2*)&g_P[(size_t)(gr + 8) * D + gc] = make_float2(acc[mt][nt][2], acc[mt][nt][3]);
            }
    }
}

// ---------------- agg: h1 build + h2 HMMA + softmax + aggregate --------------
__global__ void __launch_bounds__(128) agg_kernel(
    const float* __restrict__ V, const int* __restrict__ neigh,
    const float* __restrict__ b2, const float* __restrict__ W3,
    float* __restrict__ out, int n_nodes, int n_tiles)
{
    extern __shared__ char dsm[];
    char* smc = (char*)(((uintptr_t)dsm + 1023) & ~(uintptr_t)1023);
    u32 sb = smem_u32(smc);
    const int t = threadIdx.x, w = t >> 5, lane = t & 31;
    const int mw = w >> 1, nw = w & 1;

    int*    idx   = (int*)(smc + IDX_OFF);
    float2* b2w3  = (float2*)(smc + BW_OFF);
    float*  spart = (float*)(smc + SP_OFF);     // [2][64]
    float*  att   = (float*)(smc + ATT_OFF);    // [64]
    float4* aggp  = (float4*)(smc + AGP_OFF);   // [4][32]

    stage_B(smc, g_Bimg[1], t);
    if (t < D) b2w3[t] = make_float2(b2[t], W3[t]);

    const float4* P4 = (const float4*)g_P;
    const float4* Q4 = (const float4*)g_Q;
    const float4* V4 = (const float4*)V;

    for (int tile = blockIdx.x; tile < n_tiles; tile += gridDim.x) {
        __syncthreads();
        const int n0 = tile * 2;
        if (t < 64) {
            int gi = n0 * 32 + t;
            int mx = n_nodes * 32 - 1; if (gi > mx) gi = mx;
            idx[t] = neigh[gi];
        }
        __syncthreads();

        // stage A = relu(P[idx] + Q[node]) as bf16 hi/lo
        #pragma unroll 4
        for (int i = 0; i < 16; i++) {
            int r = w * 16 + i;
            int vid = idx[r];
            int nd = n0 + (r >> 5); if (nd >= n_nodes) nd = n_nodes - 1;
            float4 p = P4[(size_t)vid * 32 + lane];
            float4 q = Q4[(size_t)nd * 32 + lane];
            float4 h;
            h.x = fmaxf(p.x + q.x, 0.f); h.y = fmaxf(p.y + q.y, 0.f);
            h.z = fmaxf(p.z + q.z, 0.f); h.w = fmaxf(p.w + q.w, 0.f);
            uint2 hi, lo; split4(h, hi, lo);
            u32 byte = (u32)(r * 256 + ((((u32)(lane >> 1)) ^ (u32)(r & 7)) << 4) + ((lane & 1) << 3));
            *(uint2*)(smc + A_OFF + byte) = hi;
            *(uint2*)(smc + A_OFF + 16384 + byte) = lo;
        }
        __syncthreads();

        float acc[2][8][4];
        #pragma unroll
        for (int a = 0; a < 2; a++)
            #pragma unroll
            for (int b = 0; b < 8; b++)
                #pragma unroll
                for (int c = 0; c < 4; c++) acc[a][b][c] = 0.f;

        gemm_tile(sb + A_OFF, sb + B_OFF, lane, mw, nw, acc);

        // scores: s[row] = sum_c relu(h2 + b2[c]) * W3[c]
        float sp[4] = {0.f, 0.f, 0.f, 0.f};
        #pragma unroll
        for (int mt = 0; mt < 2; mt++)
            #pragma unroll
            for (int nt = 0; nt < 8; nt++) {
                int gc = 64 * nw + 8 * nt + 2 * (lane & 3);
                float2 bw0 = b2w3[gc], bw1 = b2w3[gc + 1];
                sp[mt * 2 + 0] += fmaxf(acc[mt][nt][0] + bw0.x, 0.f) * bw0.y
                                + fmaxf(acc[mt][nt][1] + bw1.x, 0.f) * bw1.y;
                sp[mt * 2 + 1] += fmaxf(acc[mt][nt][2] + bw0.x, 0.f) * bw0.y
                                + fmaxf(acc[mt][nt][3] + bw1.x, 0.f) * bw1.y;
            }
        #pragma unroll
        for (int j = 0; j < 4; j++) {
            sp[j] += __shfl_xor_sync(0xffffffffu, sp[j], 1);
            sp[j] += __shfl_xor_sync(0xffffffffu, sp[j], 2);
        }
        if ((lane & 3) == 0) {
            #pragma unroll
            for (int mt = 0; mt < 2; mt++)
                #pragma unroll
                for (int h = 0; h < 2; h++)
                    spart[nw * 64 + 32 * mw + 16 * mt + 8 * h + (lane >> 2)] = sp[mt * 2 + h];
        }
        __syncthreads();

        if (w < 2) {   // softmax, warp w = node-local w
            float s = spart[32 * w + lane] + spart[64 + 32 * w + lane];
            float m = s;
            #pragma unroll
            for (int o = 16; o > 0; o >>= 1) m = fmaxf(m, __shfl_xor_sync(0xffffffffu, m, o));
            float ev = expf(s - m);
            float sum = ev;
            #pragma unroll
            for (int o = 16; o > 0; o >>= 1) sum += __shfl_xor_sync(0xffffffffu, sum, o);
            att[32 * w + lane] = ev / sum;
        }
        __syncthreads();

        // aggregation: warp w covers node (w>>1), k-half (w&1)
        {
            int nd = w >> 1, kh = w & 1;
            float4 a4 = make_float4(0.f, 0.f, 0.f, 0.f);
            #pragma unroll 4
            for (int kk = 0; kk < 16; kk++) {
                int k = 32 * nd + kh * 16 + kk;
                float a = att[k];
                int vid = idx[k];
                float4 v = V4[(size_t)vid * 32 + lane];
                a4.x = fmaf(a, v.x, a4.x); a4.y = fmaf(a, v.y, a4.y);
                a4.z = fmaf(a, v.z, a4.z); a4.w = fmaf(a, v.w, a4.w);
            }
            aggp[w * 32 + lane] = a4;
        }
        __syncthreads();
        if (w < 2 && (n0 + w) < n_nodes) {
            float4 p0 = aggp[(2 * w) * 32 + lane];
            float4 p1 = aggp[(2 * w + 1) * 32 + lane];
            float4 r = make_float4(p0.x + p1.x, p0.y + p1.y, p0.z + p1.z, p0.w + p1.w);
            ((float4*)out)[(size_t)(n0 + w) * 32 + lane] = r;
        }
    }
}

// -----------------------------------------------------------------------------
extern "C" void kernel_launch(void* const* d_in, const int* in_sizes, int n_in,
                              void* d_out, int out_size)
{
    const float* V     = (const float*)d_in[0];
    const int*   nodes = (const int*)  d_in[1];
    const int*   neigh = (const int*)  d_in[2];
    const float* W1    = (const float*)d_in[3];
    const float* b1    = (const float*)d_in[4];
    const float* W2    = (const float*)d_in[5];
    const float* b2    = (const float*)d_in[6];
    const float* W3    = (const float*)d_in[7];
    float* out = (float*)d_out;

    const int n_videos = in_sizes[0] / D;
    const int n_nodes  = in_sizes[1];
    const int p_tiles  = (n_videos + 63) / 64;
    const int a_tiles  = (n_nodes + 1) / 2;

    cudaFuncSetAttribute(pproj_kernel, cudaFuncAttributeMaxDynamicSharedMemorySize, SMEM_BYTES);
    cudaFuncSetAttribute(agg_kernel,   cudaFuncAttributeMaxDynamicSharedMemorySize, SMEM_BYTES);

    prep_kernel<<<2, 128>>>(W1, W2);
    qproj_kernel<<<(n_nodes + 7) / 8, 128>>>(V, W1 + D * D, b1, nodes, n_nodes);
    pproj_kernel<<<296, 128, SMEM_BYTES>>>(V, n_videos, p_tiles);
    agg_kernel<<<296, 128, SMEM_BYTES>>>(V, neigh, b2, W3, out, n_nodes, a_tiles);
}

// round 4
// speedup vs baseline: 2.5221x; 1.5453x over previous
#include <cuda_runtime.h>
#include <cuda_bf16.h>
#include <cstdint>

#define D 128
#define NV_MAX 200000
#define NN_MAX 20000

typedef unsigned long long u64;
typedef unsigned int u32;

// ---------------- device scratch (no allocs allowed) ------------------------
__device__ float g_P[(size_t)NV_MAX * D];            // V @ W1a (fp32)
__device__ float g_Q[(size_t)NN_MAX * D];            // V[nodes] @ W1b + b1
// pre-swizzled bf16 weight images: [which][ hi 32KB | lo 32KB ], 256B rows
__device__ __align__(16) unsigned char g_Bimg[2][65536];

// ---------------- smem layouts ------------------------------------------------
// agg kernel
#define AG_B    0          // B hi 32K | lo 32K
#define AG_A    65536      // A hi 16K | lo 16K
#define AG_PST  98304      // staged P rows fp32 [64][128]  (32K)
#define AG_VST  131072     // staged V rows fp32 [64][128]  (32K)
#define AG_QST  163840     // staged Q rows fp32 [2][128]   (1K)
#define AG_BW   164864     // float2 b2/W3 [128]            (1K)
#define AG_SP   165888     // score partials float[2][64]
#define AG_ATT  166400     // att float[64]
#define AG_SMEM 166912
// pproj kernel
#define PP_B    0
#define PP_A    65536
#define PP_ST   98304      // staged V rows fp32 [64][128]
#define PP_SMEM 131072

// ---------------- helpers ------------------------------------------------------
__device__ __forceinline__ u32 smem_u32(const void* p) {
    u32 a; asm("{ .reg .u64 t; cvta.to.shared.u64 t, %1; cvt.u32.u64 %0, t; }" : "=r"(a) : "l"(p));
    return a;
}
__device__ __forceinline__ void ldm_x4(u32 addr, u32* r) {
    asm volatile("ldmatrix.sync.aligned.m8n8.x4.shared.b16 {%0,%1,%2,%3}, [%4];"
        : "=r"(r[0]), "=r"(r[1]), "=r"(r[2]), "=r"(r[3]) : "r"(addr));
}
__device__ __forceinline__ void mma_bf16(float* c, const u32* a, const u32* b) {
    asm volatile("mma.sync.aligned.m16n8k16.row.col.f32.bf16.bf16.f32 "
        "{%0,%1,%2,%3}, {%4,%5,%6,%7}, {%8,%9}, {%0,%1,%2,%3};"
        : "+f"(c[0]), "+f"(c[1]), "+f"(c[2]), "+f"(c[3])
        : "r"(a[0]), "r"(a[1]), "r"(a[2]), "r"(a[3]), "r"(b[0]), "r"(b[1]));
}
__device__ __forceinline__ void cpa16(u32 dst, const void* src) {
    asm volatile("cp.async.cg.shared.global [%0], [%1], 16;" :: "r"(dst), "l"(src) : "memory");
}
#define CP_COMMIT() asm volatile("cp.async.commit_group;" ::: "memory")
#define CP_WAIT(n)  asm volatile("cp.async.wait_group %0;" :: "n"(n) : "memory")

// pack float4 into bf16 hi (8B) + bf16 lo residual (8B), k-order preserved
__device__ __forceinline__ void split4(float4 v, uint2& hi, uint2& lo) {
    u32 h01, h23;
    asm("cvt.rn.bf16x2.f32 %0, %1, %2;" : "=r"(h01) : "f"(v.y), "f"(v.x));
    asm("cvt.rn.bf16x2.f32 %0, %1, %2;" : "=r"(h23) : "f"(v.w), "f"(v.z));
    float rx = v.x - __bfloat162float(__ushort_as_bfloat16((unsigned short)(h01 & 0xffff)));
    float ry = v.y - __bfloat162float(__ushort_as_bfloat16((unsigned short)(h01 >> 16)));
    float rz = v.z - __bfloat162float(__ushort_as_bfloat16((unsigned short)(h23 & 0xffff)));
    float rw = v.w - __bfloat162float(__ushort_as_bfloat16((unsigned short)(h23 >> 16)));
    u32 l01, l23;
    asm("cvt.rn.bf16x2.f32 %0, %1, %2;" : "=r"(l01) : "f"(ry), "f"(rx));
    asm("cvt.rn.bf16x2.f32 %0, %1, %2;" : "=r"(l23) : "f"(rw), "f"(rz));
    hi = make_uint2(h01, h23); lo = make_uint2(l01, l23);
}

// ---------------- shared GEMM: block tile 64x128, warp tile 16x64, 8 warps ----
// A: [64 rows][128 k] bf16, 256B rows, 16B chunks XOR-swizzled by (row&7).
// B: [128 n][128 k] bf16 (= W^T), same row format. 3 passes: AhBh+AlBh+AhBl.
__device__ __forceinline__ void gemm16(u32 sA, u32 sB, int lane, int mw, int nw,
                                       float (&acc)[8][4]) {
    const int lr   = lane & 7;
    const int akl  = lane >> 4;
    const int arow = lr + ((lane >> 3) & 1) * 8;
    const int bkl  = (lane >> 3) & 1;
    const int brow = lr + (lane >> 4) * 8;
    const u32 aoff = (u32)((16 * mw + arow) * 256);
    u32 boff[4];
    #pragma unroll
    for (int n2 = 0; n2 < 4; n2++) boff[n2] = (u32)((64 * nw + 16 * n2 + brow) * 256);

    #pragma unroll 1
    for (int ks = 0; ks < 8; ks++) {
        const int kc0 = ks * 2;
        const u32 axor = (u32)(((kc0 + akl) ^ lr) << 4);
        const u32 bxor = (u32)(((kc0 + bkl) ^ lr) << 4);
        u32 ah[4], al[4], b[4][4];
        ldm_x4(sA + aoff + axor, ah);
        ldm_x4(sA + 16384 + aoff + axor, al);
        #pragma unroll
        for (int n2 = 0; n2 < 4; n2++) ldm_x4(sB + boff[n2] + bxor, b[n2]);
        #pragma unroll
        for (int nt = 0; nt < 8; nt++) {
            mma_bf16(acc[nt], ah, &b[nt >> 1][(nt & 1) * 2]);
            mma_bf16(acc[nt], al, &b[nt >> 1][(nt & 1) * 2]);
        }
        #pragma unroll
        for (int n2 = 0; n2 < 4; n2++) ldm_x4(sB + 32768 + boff[n2] + bxor, b[n2]);
        #pragma unroll
        for (int nt = 0; nt < 8; nt++)
            mma_bf16(acc[nt], ah, &b[nt >> 1][(nt & 1) * 2]);
    }
}

__device__ __forceinline__ void stage_B(char* smc, int boff, const unsigned char* img, int t) {
    const float4* src = (const float4*)img;
    float4* dst = (float4*)(smc + boff);
    #pragma unroll
    for (int i = 0; i < 16; i++) dst[t + 256 * i] = src[t + 256 * i];
}

// ---------------- prep: W -> transposed, split, swizzled bf16 images -----------
__global__ void prep_kernel(const float* __restrict__ W1, const float* __restrict__ W2) {
    const float* W = blockIdx.x ? W2 : W1;     // W1 rows 0..127 = W1a
    unsigned char* img = g_Bimg[blockIdx.x];
    int n = threadIdx.x;
    for (int k = 0; k < D; k++) {
        float v = W[k * D + n];
        __nv_bfloat16 h = __float2bfloat16(v);
        float rem = v - __bfloat162float(h);
        __nv_bfloat16 l = __float2bfloat16(rem);
        int o = n * 256 + ((((k >> 3) ^ (n & 7))) << 4) + ((k & 7) << 1);
        *(__nv_bfloat16*)(img + o) = h;
        *(__nv_bfloat16*)(img + 32768 + o) = l;
    }
}

// ---------------- Q projection (SIMT f32x2, small) -----------------------------
__device__ __forceinline__ u64 pack2(float x, float y) {
    u64 r; asm("mov.b64 %0, {%1, %2};" : "=l"(r) : "f"(x), "f"(y)); return r;
}
__device__ __forceinline__ void unpack2(u64 v, float& x, float& y) {
    asm("mov.b64 {%0, %1}, %2;" : "=f"(x), "=f"(y) : "l"(v));
}
__device__ __forceinline__ void fma2(u64& acc, u64 a, u64 b) {
    asm("fma.rn.f32x2 %0, %1, %2, %0;" : "+l"(acc) : "l"(a), "l"(b));
}
__global__ void __launch_bounds__(128) qproj_kernel(
    const float* __restrict__ V, const float* __restrict__ W,
    const float* __restrict__ bias, const int* __restrict__ rows, int n_rows)
{
    __shared__ float vsh[D][8];
    const int t = threadIdx.x;
    const int row0 = blockIdx.x * 8;
    #pragma unroll
    for (int r = 0; r < 8; r++) {
        int row = row0 + r; if (row >= n_rows) row = n_rows - 1;
        vsh[t][r] = V[(size_t)rows[row] * D + t];
    }
    __syncthreads();
    u64 acc[4] = {0ull, 0ull, 0ull, 0ull};
    #pragma unroll 4
    for (int e = 0; e < D; e++) {
        float w = W[e * D + t];
        u64 wp = pack2(w, w);
        ulonglong2 p0 = *(const ulonglong2*)&vsh[e][0];
        ulonglong2 p1 = *(const ulonglong2*)&vsh[e][4];
        fma2(acc[0], p0.x, wp); fma2(acc[1], p0.y, wp);
        fma2(acc[2], p1.x, wp); fma2(acc[3], p1.y, wp);
    }
    float bb = bias[t];
    #pragma unroll
    for (int rp = 0; rp < 4; rp++) {
        float x, y; unpack2(acc[rp], x, y);
        int r0 = row0 + 2 * rp, r1 = r0 + 1;
        if (r0 < n_rows) g_Q[(size_t)r0 * D + t] = x + bb;
        if (r1 < n_rows) g_Q[(size_t)r1 * D + t] = y + bb;
    }
}

// ---------------- P projection: P = V @ W1a (persistent, pipelined) -----------
__global__ void __launch_bounds__(256, 1) pproj_kernel(const float* __restrict__ V,
                                                       int n_videos, int n_tiles)
{
    extern __shared__ char smc[];
    u32 sb = smem_u32(smc);
    const int t = threadIdx.x, w = t >> 5, lane = t & 31;
    const int mw = w >> 1, nw = w & 1;
    const int r = t >> 2, cc = t & 3;

    stage_B(smc, PP_B, g_Bimg[0], t);

    // prologue: stage first tile
    {
        int gr = blockIdx.x * 64 + r; if (gr >= n_videos) gr = n_videos - 1;
        #pragma unroll
        for (int i = 0; i < 8; i++) {
            int c = cc + 4 * i;
            cpa16(sb + PP_ST + (u32)((r * 32 + c) * 16), V + (size_t)gr * D + c * 4);
        }
        CP_COMMIT();
    }

    for (int tile = blockIdx.x; tile < n_tiles; tile += gridDim.x) {
        CP_WAIT(0); __syncthreads();

        // convert staged fp32 -> bf16 hi/lo swizzled A
        {
            const float4* St = (const float4*)(smc + PP_ST);
            #pragma unroll
            for (int m = 0; m < 4; m++) {
                int j = cc + 4 * m;
                float4 f0 = St[r * 32 + 2 * j], f1 = St[r * 32 + 2 * j + 1];
                uint2 hA, lA, hB, lB; split4(f0, hA, lA); split4(f1, hB, lB);
                u32 off = (u32)(r * 256 + ((j ^ (r & 7)) << 4));
                *(uint4*)(smc + PP_A + off)         = make_uint4(hA.x, hA.y, hB.x, hB.y);
                *(uint4*)(smc + PP_A + 16384 + off) = make_uint4(lA.x, lA.y, lB.x, lB.y);
            }
        }
        __syncthreads();

        float acc[8][4];
        #pragma unroll
        for (int a = 0; a < 8; a++) { acc[a][0]=0.f; acc[a][1]=0.f; acc[a][2]=0.f; acc[a][3]=0.f; }
        gemm16(sb + PP_A, sb + PP_B, lane, mw, nw, acc);

        // prefetch next tile during epilogue
        {
            int tn = tile + gridDim.x; if (tn >= n_tiles) tn = tile;
            int gr = tn * 64 + r; if (gr >= n_videos) gr = n_videos - 1;
            #pragma unroll
            for (int i = 0; i < 8; i++) {
                int c = cc + 4 * i;
                cpa16(sb + PP_ST + (u32)((r * 32 + c) * 16), V + (size_t)gr * D + c * 4);
            }
            CP_COMMIT();
        }

        // store results
        #pragma unroll
        for (int nt = 0; nt < 8; nt++) {
            int gr0 = tile * 64 + 16 * mw + (lane >> 2);
            int gc = 64 * nw + 8 * nt + 2 * (lane & 3);
            if (gr0 < n_videos)
                *(float2*)&g_P[(size_t)gr0 * D + gc] = make_float2(acc[nt][0], acc[nt][1]);
            if (gr0 + 8 < n_videos)
                *(float2*)&g_P[(size_t)(gr0 + 8) * D + gc] = make_float2(acc[nt][2], acc[nt][3]);
        }
    }
}

// ---------------- agg: pipelined h1 build + h2 HMMA + softmax + aggregate -----
__global__ void __launch_bounds__(256, 1) agg_kernel(
    const float* __restrict__ V, const int* __restrict__ neigh,
    const float* __restrict__ b2, const float* __restrict__ W3,
    float* __restrict__ out, int n_nodes, int n_tiles)
{
    extern __shared__ char smc[];
    u32 sb = smem_u32(smc);
    const int t = threadIdx.x, w = t >> 5, lane = t & 31;
    const int mw = w >> 1, nw = w & 1;
    const int r = t >> 2, cc = t & 3;       // staging row / chunk-phase

    float2* b2w3  = (float2*)(smc + AG_BW);
    float*  spart = (float*)(smc + AG_SP);
    float*  att   = (float*)(smc + AG_ATT);

    stage_B(smc, AG_B, g_Bimg[1], t);
    if (t < D) b2w3[t] = make_float2(b2[t], W3[t]);

    // prologue: idx + stage P,Q for first tile
    int vidV = 0;
    {
        int tile0 = blockIdx.x; if (tile0 >= n_tiles) tile0 = n_tiles - 1;
        vidV = neigh[(size_t)tile0 * 64 + r];
        #pragma unroll
        for (int i = 0; i < 8; i++) {
            int c = cc + 4 * i;
            cpa16(sb + AG_PST + (u32)((r * 32 + c) * 16), g_P + (size_t)vidV * D + c * 4);
        }
        if (t < 64) {
            int qr = 2 * tile0 + (t >> 5); if (qr >= n_nodes) qr = n_nodes - 1;
            cpa16(sb + AG_QST + (u32)(t * 16), g_Q + (size_t)qr * D + (t & 31) * 4);
        }
        CP_COMMIT();
    }

    for (int tile = blockIdx.x; tile < n_tiles; tile += gridDim.x) {
        CP_WAIT(0); __syncthreads();          // P(t), Q(t) landed

        // convert: A = split(relu(P + Q))
        {
            const float4* Pst = (const float4*)(smc + AG_PST);
            const float4* Qst = (const float4*)(smc + AG_QST);
            const int nd = r >> 5;
            #pragma unroll
            for (int m = 0; m < 4; m++) {
                int j = cc + 4 * m;
                float4 p0 = Pst[r * 32 + 2 * j], p1 = Pst[r * 32 + 2 * j + 1];
                float4 q0 = Qst[nd * 32 + 2 * j], q1 = Qst[nd * 32 + 2 * j + 1];
                float4 h0, h1;
                h0.x = fmaxf(p0.x + q0.x, 0.f); h0.y = fmaxf(p0.y + q0.y, 0.f);
                h0.z = fmaxf(p0.z + q0.z, 0.f); h0.w = fmaxf(p0.w + q0.w, 0.f);
                h1.x = fmaxf(p1.x + q1.x, 0.f); h1.y = fmaxf(p1.y + q1.y, 0.f);
                h1.z = fmaxf(p1.z + q1.z, 0.f); h1.w = fmaxf(p1.w + q1.w, 0.f);
                uint2 hA, lA, hB, lB; split4(h0, hA, lA); split4(h1, hB, lB);
                u32 off = (u32)(r * 256 + ((j ^ (r & 7)) << 4));
                *(uint4*)(smc + AG_A + off)         = make_uint4(hA.x, hA.y, hB.x, hB.y);
                *(uint4*)(smc + AG_A + 16384 + off) = make_uint4(lA.x, lA.y, lB.x, lB.y);
            }
        }
        __syncthreads();                       // A ready; PST free

        // stage V(t) for the aggregation epilogue (overlaps GEMM)
        #pragma unroll
        for (int i = 0; i < 8; i++) {
            int c = cc + 4 * i;
            cpa16(sb + AG_VST + (u32)((r * 32 + c) * 16), V + (size_t)vidV * D + c * 4);
        }
        CP_COMMIT();                           // group gV

        int tnext = tile + gridDim.x; if (tnext >= n_tiles) tnext = tile;
        int vidP = neigh[(size_t)tnext * 64 + r];   // latency hidden by GEMM

        float acc[8][4];
        #pragma unroll
        for (int a = 0; a < 8; a++) { acc[a][0]=0.f; acc[a][1]=0.f; acc[a][2]=0.f; acc[a][3]=0.f; }
        gemm16(sb + AG_A, sb + AG_B, lane, mw, nw, acc);

        // stage P,Q(t+1) (overlaps scores/softmax/aggregate)
        #pragma unroll
        for (int i = 0; i < 8; i++) {
            int c = cc + 4 * i;
            cpa16(sb + AG_PST + (u32)((r * 32 + c) * 16), g_P + (size_t)vidP * D + c * 4);
        }
        if (t < 64) {
            int qr = 2 * tnext + (t >> 5); if (qr >= n_nodes) qr = n_nodes - 1;
            cpa16(sb + AG_QST + (u32)(t * 16), g_Q + (size_t)qr * D + (t & 31) * 4);
        }
        CP_COMMIT();                           // group gP

        // scores: s[row] = sum_c relu(h2 + b2) * W3
        float sp0 = 0.f, sp1 = 0.f;
        #pragma unroll
        for (int nt = 0; nt < 8; nt++) {
            int gc = 64 * nw + 8 * nt + 2 * (lane & 3);
            float2 bw0 = b2w3[gc], bw1 = b2w3[gc + 1];
            sp0 += fmaxf(acc[nt][0] + bw0.x, 0.f) * bw0.y + fmaxf(acc[nt][1] + bw1.x, 0.f) * bw1.y;
            sp1 += fmaxf(acc[nt][2] + bw0.x, 0.f) * bw0.y + fmaxf(acc[nt][3] + bw1.x, 0.f) * bw1.y;
        }
        sp0 += __shfl_xor_sync(0xffffffffu, sp0, 1); sp0 += __shfl_xor_sync(0xffffffffu, sp0, 2);
        sp1 += __shfl_xor_sync(0xffffffffu, sp1, 1); sp1 += __shfl_xor_sync(0xffffffffu, sp1, 2);
        if ((lane & 3) == 0) {
            spart[nw * 64 + 16 * mw + (lane >> 2)]     = sp0;
            spart[nw * 64 + 16 * mw + 8 + (lane >> 2)] = sp1;
        }
        __syncthreads();

        if (w < 2) {                           // softmax: warp w = node-local w
            float s = spart[32 * w + lane] + spart[64 + 32 * w + lane];
            float m = s;
            #pragma unroll
            for (int o = 16; o > 0; o >>= 1) m = fmaxf(m, __shfl_xor_sync(0xffffffffu, m, o));
            float ev = expf(s - m);
            float sum = ev;
            #pragma unroll
            for (int o = 16; o > 0; o >>= 1) sum += __shfl_xor_sync(0xffffffffu, sum, o);
            att[32 * w + lane] = ev / sum;
        }
        __syncthreads();

        CP_WAIT(1); __syncthreads();           // V(t) landed (P(t+1) may fly)

        if (t < 64) {                          // aggregate from smem-resident V
            int nd = t >> 5, c4 = t & 31;
            const float4* Vst = (const float4*)(smc + AG_VST);
            float4 a4 = make_float4(0.f, 0.f, 0.f, 0.f);
            #pragma unroll 8
            for (int k = 0; k < 32; k++) {
                float a = att[32 * nd + k];
                float4 v = Vst[(32 * nd + k) * 32 + c4];
                a4.x = fmaf(a, v.x, a4.x); a4.y = fmaf(a, v.y, a4.y);
                a4.z = fmaf(a, v.z, a4.z); a4.w = fmaf(a, v.w, a4.w);
            }
            int ng = 2 * tile + nd;
            if (ng < n_nodes) ((float4*)out)[(size_t)ng * 32 + c4] = a4;
        }

        vidV = vidP;
    }
}

// -------------------------------------------------------------------------------
extern "C" void kernel_launch(void* const* d_in, const int* in_sizes, int n_in,
                              void* d_out, int out_size)
{
    const float* V     = (const float*)d_in[0];
    const int*   nodes = (const int*)  d_in[1];
    const int*   neigh = (const int*)  d_in[2];
    const float* W1    = (const float*)d_in[3];
    const float* b1    = (const float*)d_in[4];
    const float* W2    = (const float*)d_in[5];
    const float* b2    = (const float*)d_in[6];
    const float* W3    = (const float*)d_in[7];
    float* out = (float*)d_out;

    const int n_videos = in_sizes[0] / D;
    const int n_nodes  = in_sizes[1];
    const int p_tiles  = (n_videos + 63) / 64;
    const int a_tiles  = (n_nodes + 1) / 2;

    cudaFuncSetAttribute(pproj_kernel, cudaFuncAttributeMaxDynamicSharedMemorySize, PP_SMEM);
    cudaFuncSetAttribute(agg_kernel,   cudaFuncAttributeMaxDynamicSharedMemorySize, AG_SMEM);

    prep_kernel<<<2, 128>>>(W1, W2);
    qproj_kernel<<<(n_nodes + 7) / 8, 128>>>(V, W1 + D * D, b1, nodes, n_nodes);
    pproj_kernel<<<148, 256, PP_SMEM>>>(V, n_videos, p_tiles);
    agg_kernel<<<148, 256, AG_SMEM>>>(V, neigh, b2, W3, out, n_nodes, a_tiles);
}

// round 5
// speedup vs baseline: 2.7455x; 1.0886x over previous
#include <cuda_runtime.h>
#include <cuda_bf16.h>
#include <cstdint>

#define D 128
#define NV_MAX 200000
#define NN_MAX 20000

typedef unsigned long long u64;
typedef unsigned int u32;

// ---------------- device scratch (no allocs allowed) ------------------------
__device__ float g_P[(size_t)NV_MAX * D];            // V @ W1a (fp32)
__device__ float g_Q[(size_t)NN_MAX * D];            // V[nodes] @ W1b + b1
// pre-swizzled bf16 weight images: [which][ hi 32KB | lo 32KB ], 256B rows
__device__ __align__(16) unsigned char g_Bimg[2][65536];

// ---------------- smem layouts ------------------------------------------------
// agg kernel (total ~101 KB -> 2 CTAs/SM)
#define AG_B    0          // B hi 32K | lo 32K
#define AG_A    65536      // A hi 16K | lo 16K  (reused post-GEMM for agg partials)
#define AG_BW   98304      // float2 b2/W3 [128]            (1K)
#define AG_QST  99328      // float4 q rows [2buf][2node][32] (2K)
#define AG_IDX  101376     // int [2buf][64]                 (512B)
#define AG_SP   101888     // score partials float[2][64]    (512B)
#define AG_ATT  102400     // att float[64]                  (256B)
#define AG_SMEM 102912
// pproj kernel (96 KB -> 2 CTAs/SM)
#define PP_B    0
#define PP_A    65536
#define PP_SMEM 98304

// ---------------- helpers ------------------------------------------------------
__device__ __forceinline__ u32 smem_u32(const void* p) {
    u32 a; asm("{ .reg .u64 t; cvta.to.shared.u64 t, %1; cvt.u32.u64 %0, t; }" : "=r"(a) : "l"(p));
    return a;
}
__device__ __forceinline__ void ldm_x4(u32 addr, u32* r) {
    asm volatile("ldmatrix.sync.aligned.m8n8.x4.shared.b16 {%0,%1,%2,%3}, [%4];"
        : "=r"(r[0]), "=r"(r[1]), "=r"(r[2]), "=r"(r[3]) : "r"(addr));
}
__device__ __forceinline__ void mma_bf16(float* c, const u32* a, const u32* b) {
    asm volatile("mma.sync.aligned.m16n8k16.row.col.f32.bf16.bf16.f32 "
        "{%0,%1,%2,%3}, {%4,%5,%6,%7}, {%8,%9}, {%0,%1,%2,%3};"
        : "+f"(c[0]), "+f"(c[1]), "+f"(c[2]), "+f"(c[3])
        : "r"(a[0]), "r"(a[1]), "r"(a[2]), "r"(a[3]), "r"(b[0]), "r"(b[1]));
}
// pack float4 into bf16 hi (8B) + bf16 lo residual (8B), k-order preserved
__device__ __forceinline__ void split4(float4 v, uint2& hi, uint2& lo) {
    u32 h01, h23;
    asm("cvt.rn.bf16x2.f32 %0, %1, %2;" : "=r"(h01) : "f"(v.y), "f"(v.x));
    asm("cvt.rn.bf16x2.f32 %0, %1, %2;" : "=r"(h23) : "f"(v.w), "f"(v.z));
    float rx = v.x - __bfloat162float(__ushort_as_bfloat16((unsigned short)(h01 & 0xffff)));
    float ry = v.y - __bfloat162float(__ushort_as_bfloat16((unsigned short)(h01 >> 16)));
    float rz = v.z - __bfloat162float(__ushort_as_bfloat16((unsigned short)(h23 & 0xffff)));
    float rw = v.w - __bfloat162float(__ushort_as_bfloat16((unsigned short)(h23 >> 16)));
    u32 l01, l23;
    asm("cvt.rn.bf16x2.f32 %0, %1, %2;" : "=r"(l01) : "f"(ry), "f"(rx));
    asm("cvt.rn.bf16x2.f32 %0, %1, %2;" : "=r"(l23) : "f"(rw), "f"(rz));
    hi = make_uint2(h01, h23); lo = make_uint2(l01, l23);
}

// ---------------- shared GEMM: block tile 64x128, warp tile 16x64, 8 warps ----
__device__ __forceinline__ void gemm16(u32 sA, u32 sB, int lane, int mw, int nw,
                                       float (&acc)[8][4]) {
    const int lr   = lane & 7;
    const int akl  = lane >> 4;
    const int arow = lr + ((lane >> 3) & 1) * 8;
    const int bkl  = (lane >> 3) & 1;
    const int brow = lr + (lane >> 4) * 8;
    const u32 aoff = (u32)((16 * mw + arow) * 256);
    u32 boff[4];
    #pragma unroll
    for (int n2 = 0; n2 < 4; n2++) boff[n2] = (u32)((64 * nw + 16 * n2 + brow) * 256);

    #pragma unroll 1
    for (int ks = 0; ks < 8; ks++) {
        const int kc0 = ks * 2;
        const u32 axor = (u32)(((kc0 + akl) ^ lr) << 4);
        const u32 bxor = (u32)(((kc0 + bkl) ^ lr) << 4);
        u32 ah[4], al[4], b[4][4];
        ldm_x4(sA + aoff + axor, ah);
        ldm_x4(sA + 16384 + aoff + axor, al);
        #pragma unroll
        for (int n2 = 0; n2 < 4; n2++) ldm_x4(sB + boff[n2] + bxor, b[n2]);
        #pragma unroll
        for (int nt = 0; nt < 8; nt++) {
            mma_bf16(acc[nt], ah, &b[nt >> 1][(nt & 1) * 2]);
            mma_bf16(acc[nt], al, &b[nt >> 1][(nt & 1) * 2]);
        }
        #pragma unroll
        for (int n2 = 0; n2 < 4; n2++) ldm_x4(sB + 32768 + boff[n2] + bxor, b[n2]);
        #pragma unroll
        for (int nt = 0; nt < 8; nt++)
            mma_bf16(acc[nt], ah, &b[nt >> 1][(nt & 1) * 2]);
    }
}

__device__ __forceinline__ void stage_B(char* smc, int boff, const unsigned char* img, int t) {
    const float4* src = (const float4*)img;
    float4* dst = (float4*)(smc + boff);
    #pragma unroll
    for (int i = 0; i < 16; i++) dst[t + 256 * i] = src[t + 256 * i];
}

// ---------------- prep: W -> transposed, split, swizzled bf16 images -----------
__global__ void prep_kernel(const float* __restrict__ W1, const float* __restrict__ W2) {
    const float* W = blockIdx.x ? W2 : W1;     // W1 rows 0..127 = W1a
    unsigned char* img = g_Bimg[blockIdx.x];
    int n = threadIdx.x;
    for (int k = 0; k < D; k++) {
        float v = W[k * D + n];
        __nv_bfloat16 h = __float2bfloat16(v);
        float rem = v - __bfloat162float(h);
        __nv_bfloat16 l = __float2bfloat16(rem);
        int o = n * 256 + ((((k >> 3) ^ (n & 7))) << 4) + ((k & 7) << 1);
        *(__nv_bfloat16*)(img + o) = h;
        *(__nv_bfloat16*)(img + 32768 + o) = l;
    }
}

// ---------------- Q projection (SIMT f32x2, small) -----------------------------
__device__ __forceinline__ u64 pack2(float x, float y) {
    u64 r; asm("mov.b64 %0, {%1, %2};" : "=l"(r) : "f"(x), "f"(y)); return r;
}
__device__ __forceinline__ void unpack2(u64 v, float& x, float& y) {
    asm("mov.b64 {%0, %1}, %2;" : "=f"(x), "=f"(y) : "l"(v));
}
__device__ __forceinline__ void fma2(u64& acc, u64 a, u64 b) {
    asm("fma.rn.f32x2 %0, %1, %2, %0;" : "+l"(acc) : "l"(a), "l"(b));
}
__global__ void __launch_bounds__(128) qproj_kernel(
    const float* __restrict__ V, const float* __restrict__ W,
    const float* __restrict__ bias, const int* __restrict__ rows, int n_rows)
{
    __shared__ float vsh[D][8];
    const int t = threadIdx.x;
    const int row0 = blockIdx.x * 8;
    #pragma unroll
    for (int r = 0; r < 8; r++) {
        int row = row0 + r; if (row >= n_rows) row = n_rows - 1;
        vsh[t][r] = V[(size_t)rows[row] * D + t];
    }
    __syncthreads();
    u64 acc[4] = {0ull, 0ull, 0ull, 0ull};
    #pragma unroll 4
    for (int e = 0; e < D; e++) {
        float w = W[e * D + t];
        u64 wp = pack2(w, w);
        ulonglong2 p0 = *(const ulonglong2*)&vsh[e][0];
        ulonglong2 p1 = *(const ulonglong2*)&vsh[e][4];
        fma2(acc[0], p0.x, wp); fma2(acc[1], p0.y, wp);
        fma2(acc[2], p1.x, wp); fma2(acc[3], p1.y, wp);
    }
    float bb = bias[t];
    #pragma unroll
    for (int rp = 0; rp < 4; rp++) {
        float x, y; unpack2(acc[rp], x, y);
        int r0 = row0 + 2 * rp, r1 = r0 + 1;
        if (r0 < n_rows) g_Q[(size_t)r0 * D + t] = x + bb;
        if (r1 < n_rows) g_Q[(size_t)r1 * D + t] = y + bb;
    }
}

// ---------------- P projection: P = V @ W1a (persistent, 2 CTAs/SM) -----------
__global__ void __launch_bounds__(256, 2) pproj_kernel(const float* __restrict__ V,
                                                       int n_videos, int n_tiles)
{
    extern __shared__ char smc[];
    u32 sb = smem_u32(smc);
    const int t = threadIdx.x, w = t >> 5, lane = t & 31;
    const int mw = w >> 1, nw = w & 1;
    const int r = t >> 2, cc = t & 3;

    stage_B(smc, PP_B, g_Bimg[0], t);
    const float4* V4 = (const float4*)V;

    for (int tile = blockIdx.x; tile < n_tiles; tile += gridDim.x) {
        __syncthreads();
        // convert: direct LDG of V rows -> bf16 hi/lo swizzled A
        {
            int gr = tile * 64 + r; if (gr >= n_videos) gr = n_videos - 1;
            const float4* Vr = V4 + (size_t)gr * 32;
            #pragma unroll
            for (int m = 0; m < 4; m++) {
                int j = cc + 4 * m;
                float4 f0 = Vr[2 * j], f1 = Vr[2 * j + 1];
                uint2 hA, lA, hB, lB; split4(f0, hA, lA); split4(f1, hB, lB);
                u32 off = (u32)(r * 256 + ((j ^ (r & 7)) << 4));
                *(uint4*)(smc + PP_A + off)         = make_uint4(hA.x, hA.y, hB.x, hB.y);
                *(uint4*)(smc + PP_A + 16384 + off) = make_uint4(lA.x, lA.y, lB.x, lB.y);
            }
        }
        __syncthreads();

        float acc[8][4];
        #pragma unroll
        for (int a = 0; a < 8; a++) { acc[a][0]=0.f; acc[a][1]=0.f; acc[a][2]=0.f; acc[a][3]=0.f; }
        gemm16(sb + PP_A, sb + PP_B, lane, mw, nw, acc);

        #pragma unroll
        for (int nt = 0; nt < 8; nt++) {
            int gr0 = tile * 64 + 16 * mw + (lane >> 2);
            int gc = 64 * nw + 8 * nt + 2 * (lane & 3);
            if (gr0 < n_videos)
                *(float2*)&g_P[(size_t)gr0 * D + gc] = make_float2(acc[nt][0], acc[nt][1]);
            if (gr0 + 8 < n_videos)
                *(float2*)&g_P[(size_t)(gr0 + 8) * D + gc] = make_float2(acc[nt][2], acc[nt][3]);
        }
    }
}

// ---------------- agg: h1 + h2 HMMA + softmax + aggregate (2 CTAs/SM) ----------
__global__ void __launch_bounds__(256, 2) agg_kernel(
    const float* __restrict__ V, const int* __restrict__ neigh,
    const float* __restrict__ b2, const float* __restrict__ W3,
    float* __restrict__ out, int n_nodes, int n_tiles)
{
    extern __shared__ char smc[];
    u32 sb = smem_u32(smc);
    const int t = threadIdx.x, w = t >> 5, lane = t & 31;
    const int mw = w >> 1, nw = w & 1;
    const int r = t >> 2, cc = t & 3;

    float2* b2w3  = (float2*)(smc + AG_BW);
    float4* qst4  = (float4*)(smc + AG_QST);   // [2buf][2node][32]
    int*    idx_s = (int*)(smc + AG_IDX);      // [2buf][64]
    float*  spart = (float*)(smc + AG_SP);
    float*  att   = (float*)(smc + AG_ATT);
    float4* pp4   = (float4*)(smc + AG_A);     // partials overlay (post-GEMM)

    stage_B(smc, AG_B, g_Bimg[1], t);
    if (t < D) b2w3[t] = make_float2(b2[t], W3[t]);

    const float4* P4 = (const float4*)g_P;
    const float4* Q4 = (const float4*)g_Q;
    const float4* V4 = (const float4*)V;

    // prologue: idx + Q for first tile into buffer 0
    {
        int tile0 = blockIdx.x; if (tile0 >= n_tiles) tile0 = n_tiles - 1;
        if (t < 64) {
            idx_s[t] = neigh[(size_t)tile0 * 64 + t];
            int qr = 2 * tile0 + (t >> 5); if (qr >= n_nodes) qr = n_nodes - 1;
            qst4[t] = Q4[(size_t)qr * 32 + (t & 31)];
        }
    }
    __syncthreads();
    int vidr = idx_s[r];
    int bp = 0;

    for (int tile = blockIdx.x; tile < n_tiles; tile += gridDim.x) {
        const int cur = bp, nxt = bp ^ 1;

        // convert: A = split(relu(P[vid] + Q[node])), P via direct LDG
        {
            const float4* Pr = P4 + (size_t)vidr * 32;
            const float4* Qr = qst4 + cur * 64 + (r >> 5) * 32;
            #pragma unroll
            for (int m = 0; m < 4; m++) {
                int j = cc + 4 * m;
                float4 p0 = Pr[2 * j], p1 = Pr[2 * j + 1];
                float4 q0 = Qr[2 * j], q1 = Qr[2 * j + 1];
                float4 h0, h1;
                h0.x = fmaxf(p0.x + q0.x, 0.f); h0.y = fmaxf(p0.y + q0.y, 0.f);
                h0.z = fmaxf(p0.z + q0.z, 0.f); h0.w = fmaxf(p0.w + q0.w, 0.f);
                h1.x = fmaxf(p1.x + q1.x, 0.f); h1.y = fmaxf(p1.y + q1.y, 0.f);
                h1.z = fmaxf(p1.z + q1.z, 0.f); h1.w = fmaxf(p1.w + q1.w, 0.f);
                uint2 hA, lA, hB, lB; split4(h0, hA, lA); split4(h1, hB, lB);
                u32 off = (u32)(r * 256 + ((j ^ (r & 7)) << 4));
                *(uint4*)(smc + AG_A + off)         = make_uint4(hA.x, hA.y, hB.x, hB.y);
                *(uint4*)(smc + AG_A + 16384 + off) = make_uint4(lA.x, lA.y, lB.x, lB.y);
            }
        }
        __syncthreads();

        // prefetch next tile's idx + Q (LDGs scheduled before GEMM, hidden by it)
        int tnext = tile + gridDim.x; if (tnext >= n_tiles) tnext = tile;
        if (t < 64) {
            idx_s[nxt * 64 + t] = neigh[(size_t)tnext * 64 + t];
            int qr = 2 * tnext + (t >> 5); if (qr >= n_nodes) qr = n_nodes - 1;
            qst4[nxt * 64 + t] = Q4[(size_t)qr * 32 + (t & 31)];
        }

        float acc[8][4];
        #pragma unroll
        for (int a = 0; a < 8; a++) { acc[a][0]=0.f; acc[a][1]=0.f; acc[a][2]=0.f; acc[a][3]=0.f; }
        gemm16(sb + AG_A, sb + AG_B, lane, mw, nw, acc);

        // scores: s[row] = sum_c relu(h2 + b2) * W3
        float sp0 = 0.f, sp1 = 0.f;
        #pragma unroll
        for (int nt = 0; nt < 8; nt++) {
            int gc = 64 * nw + 8 * nt + 2 * (lane & 3);
            float2 bw0 = b2w3[gc], bw1 = b2w3[gc + 1];
            sp0 += fmaxf(acc[nt][0] + bw0.x, 0.f) * bw0.y + fmaxf(acc[nt][1] + bw1.x, 0.f) * bw1.y;
            sp1 += fmaxf(acc[nt][2] + bw0.x, 0.f) * bw0.y + fmaxf(acc[nt][3] + bw1.x, 0.f) * bw1.y;
        }
        sp0 += __shfl_xor_sync(0xffffffffu, sp0, 1); sp0 += __shfl_xor_sync(0xffffffffu, sp0, 2);
        sp1 += __shfl_xor_sync(0xffffffffu, sp1, 1); sp1 += __shfl_xor_sync(0xffffffffu, sp1, 2);
        if ((lane & 3) == 0) {
            spart[nw * 64 + 16 * mw + (lane >> 2)]     = sp0;
            spart[nw * 64 + 16 * mw + 8 + (lane >> 2)] = sp1;
        }
        __syncthreads();                       // also guarantees GEMM done (A reusable)

        if (w < 2) {                           // softmax: warp w = node-local w
            float s = spart[32 * w + lane] + spart[64 + 32 * w + lane];
            float m = s;
            #pragma unroll
            for (int o = 16; o > 0; o >>= 1) m = fmaxf(m, __shfl_xor_sync(0xffffffffu, m, o));
            float ev = expf(s - m);
            float sum = ev;
            #pragma unroll
            for (int o = 16; o > 0; o >>= 1) sum += __shfl_xor_sync(0xffffffffu, sum, o);
            att[32 * w + lane] = ev / sum;
        }
        __syncthreads();

        // aggregate: 256-thread partials (direct LDG of V), reduce in A overlay
        {
            int nd = t >> 7, sub = (t >> 5) & 3, c4 = t & 31;
            float4 a4 = make_float4(0.f, 0.f, 0.f, 0.f);
            #pragma unroll
            for (int kk = 0; kk < 8; kk++) {
                int k = 32 * nd + 8 * sub + kk;
                float a = att[k];
                int vid = idx_s[cur * 64 + k];
                float4 v = V4[(size_t)vid * 32 + c4];
                a4.x = fmaf(a, v.x, a4.x); a4.y = fmaf(a, v.y, a4.y);
                a4.z = fmaf(a, v.z, a4.z); a4.w = fmaf(a, v.w, a4.w);
            }
            pp4[(nd * 4 + sub) * 32 + c4] = a4;
        }
        __syncthreads();
        if (t < 64) {
            int nd = t >> 5, c4 = t & 31;
            float4 s0 = pp4[(nd * 4 + 0) * 32 + c4];
            float4 s1 = pp4[(nd * 4 + 1) * 32 + c4];
            float4 s2 = pp4[(nd * 4 + 2) * 32 + c4];
            float4 s3 = pp4[(nd * 4 + 3) * 32 + c4];
            float4 rr = make_float4(s0.x + s1.x + s2.x + s3.x, s0.y + s1.y + s2.y + s3.y,
                                    s0.z + s1.z + s2.z + s3.z, s0.w + s1.w + s2.w + s3.w);
            int ng = 2 * tile + nd;
            if (ng < n_nodes) ((float4*)out)[(size_t)ng * 32 + c4] = rr;
        }
        __syncthreads();                       // A overlay free before next convert

        vidr = idx_s[nxt * 64 + r];
        bp ^= 1;
    }
}

// -------------------------------------------------------------------------------
extern "C" void kernel_launch(void* const* d_in, const int* in_sizes, int n_in,
                              void* d_out, int out_size)
{
    const float* V     = (const float*)d_in[0];
    const int*   nodes = (const int*)  d_in[1];
    const int*   neigh = (const int*)  d_in[2];
    const float* W1    = (const float*)d_in[3];
    const float* b1    = (const float*)d_in[4];
    const float* W2    = (const float*)d_in[5];
    const float* b2    = (const float*)d_in[6];
    const float* W3    = (const float*)d_in[7];
    float* out = (float*)d_out;

    const int n_videos = in_sizes[0] / D;
    const int n_nodes  = in_sizes[1];
    const int p_tiles  = (n_videos + 63) / 64;
    const int a_tiles  = (n_nodes + 1) / 2;

    cudaFuncSetAttribute(pproj_kernel, cudaFuncAttributeMaxDynamicSharedMemorySize, PP_SMEM);
    cudaFuncSetAttribute(agg_kernel,   cudaFuncAttributeMaxDynamicSharedMemorySize, AG_SMEM);

    prep_kernel<<<2, 128>>>(W1, W2);
    qproj_kernel<<<(n_nodes + 7) / 8, 128>>>(V, W1 + D * D, b1, nodes, n_nodes);
    pproj_kernel<<<296, 256, PP_SMEM>>>(V, n_videos, p_tiles);
    agg_kernel<<<296, 256, AG_SMEM>>>(V, neigh, b2, W3, out, n_nodes, a_tiles);
}

// round 6
// speedup vs baseline: 3.3280x; 1.2122x over previous
#include <cuda_runtime.h>
#include <cuda_bf16.h>
#include <cuda_fp16.h>
#include <cstdint>

#define D 128
#define NV_MAX 200000
#define NN_MAX 20000

typedef unsigned long long u64;
typedef unsigned int u32;

// ---------------- device scratch (no allocs allowed) ------------------------
__device__ float g_P[(size_t)NV_MAX * D];            // V @ W1a (fp32)
__device__ float g_Q[(size_t)NN_MAX * D];            // V[nodes] @ W1b + b1
__device__ __align__(16) unsigned char g_Bimg[65536];  // W1a^T bf16 hi|lo (pproj)
__device__ __align__(16) unsigned char g_W2h[32768];   // W2^T fp16 (agg, single)

// ---------------- smem layouts ------------------------------------------------
// agg kernel (~104 KB -> 2 CTAs/SM)
#define AG_B    0          // B fp16 32K
#define AG_A    32768      // A fp16 hi 32K | lo 32K (overlay: agg partials)
#define AG_BW   98304      // float2 b2/W3 [128]         (1K)
#define AG_QST  99328      // float4 q rows [2buf][128]  (4K)
#define AG_IDX  103424     // int [2buf][128]            (1K)
#define AG_SP   104448     // score partials float[2][128] (1K)
#define AG_ATT  105472     // att float[128]             (512B)
#define AG_SMEM 106496
// pproj kernel (96 KB -> 2 CTAs/SM)
#define PP_B    0
#define PP_A    65536
#define PP_SMEM 98304

// ---------------- helpers ------------------------------------------------------
__device__ __forceinline__ u32 smem_u32(const void* p) {
    u32 a; asm("{ .reg .u64 t; cvta.to.shared.u64 t, %1; cvt.u32.u64 %0, t; }" : "=r"(a) : "l"(p));
    return a;
}
__device__ __forceinline__ void ldm_x4(u32 addr, u32* r) {
    asm volatile("ldmatrix.sync.aligned.m8n8.x4.shared.b16 {%0,%1,%2,%3}, [%4];"
        : "=r"(r[0]), "=r"(r[1]), "=r"(r[2]), "=r"(r[3]) : "r"(addr));
}
__device__ __forceinline__ void mma_bf16(float* c, const u32* a, const u32* b) {
    asm volatile("mma.sync.aligned.m16n8k16.row.col.f32.bf16.bf16.f32 "
        "{%0,%1,%2,%3}, {%4,%5,%6,%7}, {%8,%9}, {%0,%1,%2,%3};"
        : "+f"(c[0]), "+f"(c[1]), "+f"(c[2]), "+f"(c[3])
        : "r"(a[0]), "r"(a[1]), "r"(a[2]), "r"(a[3]), "r"(b[0]), "r"(b[1]));
}
__device__ __forceinline__ void mma_f16(float* c, const u32* a, const u32* b) {
    asm volatile("mma.sync.aligned.m16n8k16.row.col.f32.f16.f16.f32 "
        "{%0,%1,%2,%3}, {%4,%5,%6,%7}, {%8,%9}, {%0,%1,%2,%3};"
        : "+f"(c[0]), "+f"(c[1]), "+f"(c[2]), "+f"(c[3])
        : "r"(a[0]), "r"(a[1]), "r"(a[2]), "r"(a[3]), "r"(b[0]), "r"(b[1]));
}
// bf16 split (pproj path)
__device__ __forceinline__ void split4(float4 v, uint2& hi, uint2& lo) {
    u32 h01, h23;
    asm("cvt.rn.bf16x2.f32 %0, %1, %2;" : "=r"(h01) : "f"(v.y), "f"(v.x));
    asm("cvt.rn.bf16x2.f32 %0, %1, %2;" : "=r"(h23) : "f"(v.w), "f"(v.z));
    float rx = v.x - __bfloat162float(__ushort_as_bfloat16((unsigned short)(h01 & 0xffff)));
    float ry = v.y - __bfloat162float(__ushort_as_bfloat16((unsigned short)(h01 >> 16)));
    float rz = v.z - __bfloat162float(__ushort_as_bfloat16((unsigned short)(h23 & 0xffff)));
    float rw = v.w - __bfloat162float(__ushort_as_bfloat16((unsigned short)(h23 >> 16)));
    u32 l01, l23;
    asm("cvt.rn.bf16x2.f32 %0, %1, %2;" : "=r"(l01) : "f"(ry), "f"(rx));
    asm("cvt.rn.bf16x2.f32 %0, %1, %2;" : "=r"(l23) : "f"(rw), "f"(rz));
    hi = make_uint2(h01, h23); lo = make_uint2(l01, l23);
}
// fp16 split (agg path): hi = f16(x), lo = f16(x - hi)
__device__ __forceinline__ void split4h(float4 v, uint2& hi, uint2& lo) {
    __half2 h01 = __floats2half2_rn(v.x, v.y);
    __half2 h23 = __floats2half2_rn(v.z, v.w);
    float rx = v.x - __half2float(__low2half(h01));
    float ry = v.y - __half2float(__high2half(h01));
    float rz = v.z - __half2float(__low2half(h23));
    float rw = v.w - __half2float(__high2half(h23));
    __half2 l01 = __floats2half2_rn(rx, ry);
    __half2 l23 = __floats2half2_rn(rz, rw);
    hi = make_uint2(*(u32*)&h01, *(u32*)&h23);
    lo = make_uint2(*(u32*)&l01, *(u32*)&l23);
}

// ---------------- pproj GEMM (bf16 3-pass, warp 16x64, M=64) -------------------
__device__ __forceinline__ void gemm16(u32 sA, u32 sB, int lane, int mw, int nw,
                                       float (&acc)[8][4]) {
    const int lr   = lane & 7;
    const int akl  = lane >> 4;
    const int arow = lr + ((lane >> 3) & 1) * 8;
    const int bkl  = (lane >> 3) & 1;
    const int brow = lr + (lane >> 4) * 8;
    const u32 aoff = (u32)((16 * mw + arow) * 256);
    u32 boff[4];
    #pragma unroll
    for (int n2 = 0; n2 < 4; n2++) boff[n2] = (u32)((64 * nw + 16 * n2 + brow) * 256);

    #pragma unroll 1
    for (int ks = 0; ks < 8; ks++) {
        const int kc0 = ks * 2;
        const u32 axor = (u32)(((kc0 + akl) ^ lr) << 4);
        const u32 bxor = (u32)(((kc0 + bkl) ^ lr) << 4);
        u32 ah[4], al[4], b[4][4];
        ldm_x4(sA + aoff + axor, ah);
        ldm_x4(sA + 16384 + aoff + axor, al);
        #pragma unroll
        for (int n2 = 0; n2 < 4; n2++) ldm_x4(sB + boff[n2] + bxor, b[n2]);
        #pragma unroll
        for (int nt = 0; nt < 8; nt++) {
            mma_bf16(acc[nt], ah, &b[nt >> 1][(nt & 1) * 2]);
            mma_bf16(acc[nt], al, &b[nt >> 1][(nt & 1) * 2]);
        }
        #pragma unroll
        for (int n2 = 0; n2 < 4; n2++) ldm_x4(sB + 32768 + boff[n2] + bxor, b[n2]);
        #pragma unroll
        for (int nt = 0; nt < 8; nt++)
            mma_bf16(acc[nt], ah, &b[nt >> 1][(nt & 1) * 2]);
    }
}

// ---------------- agg GEMM (fp16 2-pass, warp 32x64, M=128) --------------------
__device__ __forceinline__ void gemm32_f16(u32 sA, u32 sB, int lane, int mw, int nw,
                                           float (&acc)[2][8][4]) {
    const int lr   = lane & 7;
    const int akl  = lane >> 4;
    const int arow = lr + ((lane >> 3) & 1) * 8;
    const int bkl  = (lane >> 3) & 1;
    const int brow = lr + (lane >> 4) * 8;
    u32 aoffm[2];
    #pragma unroll
    for (int mt = 0; mt < 2; mt++) aoffm[mt] = (u32)((32 * mw + 16 * mt + arow) * 256);
    u32 boff[4];
    #pragma unroll
    for (int n2 = 0; n2 < 4; n2++) boff[n2] = (u32)((64 * nw + 16 * n2 + brow) * 256);

    #pragma unroll 1
    for (int ks = 0; ks < 8; ks++) {
        const int kc0 = ks * 2;
        const u32 axor = (u32)(((kc0 + akl) ^ lr) << 4);
        const u32 bxor = (u32)(((kc0 + bkl) ^ lr) << 4);
        u32 ah[2][4], al[2][4], b[4][4];
        #pragma unroll
        for (int mt = 0; mt < 2; mt++) {
            ldm_x4(sA + aoffm[mt] + axor, ah[mt]);
            ldm_x4(sA + 32768 + aoffm[mt] + axor, al[mt]);
        }
        #pragma unroll
        for (int n2 = 0; n2 < 4; n2++) ldm_x4(sB + boff[n2] + bxor, b[n2]);
        #pragma unroll
        for (int mt = 0; mt < 2; mt++)
            #pragma unroll
            for (int nt = 0; nt < 8; nt++) {
                mma_f16(acc[mt][nt], ah[mt], &b[nt >> 1][(nt & 1) * 2]);
                mma_f16(acc[mt][nt], al[mt], &b[nt >> 1][(nt & 1) * 2]);
            }
    }
}

// ---------------- prep: weights -> transposed, split, swizzled images ----------
__global__ void prep_kernel(const float* __restrict__ W1, const float* __restrict__ W2) {
    int n = threadIdx.x;
    if (blockIdx.x == 0) {                      // W1a -> bf16 hi/lo (pproj)
        for (int k = 0; k < D; k++) {
            float v = W1[k * D + n];
            __nv_bfloat16 h = __float2bfloat16(v);
            float rem = v - __bfloat162float(h);
            __nv_bfloat16 l = __float2bfloat16(rem);
            int o = n * 256 + ((((k >> 3) ^ (n & 7))) << 4) + ((k & 7) << 1);
            *(__nv_bfloat16*)(g_Bimg + o) = h;
            *(__nv_bfloat16*)(g_Bimg + 32768 + o) = l;
        }
    } else {                                    // W2 -> fp16 single (agg)
        for (int k = 0; k < D; k++) {
            float v = W2[k * D + n];
            __half h = __float2half_rn(v);
            int o = n * 256 + ((((k >> 3) ^ (n & 7))) << 4) + ((k & 7) << 1);
            *(__half*)(g_W2h + o) = h;
        }
    }
}

// ---------------- Q projection (SIMT f32x2, small) -----------------------------
__device__ __forceinline__ u64 pack2(float x, float y) {
    u64 r; asm("mov.b64 %0, {%1, %2};" : "=l"(r) : "f"(x), "f"(y)); return r;
}
__device__ __forceinline__ void unpack2(u64 v, float& x, float& y) {
    asm("mov.b64 {%0, %1}, %2;" : "=f"(x), "=f"(y) : "l"(v));
}
__device__ __forceinline__ void fma2(u64& acc, u64 a, u64 b) {
    asm("fma.rn.f32x2 %0, %1, %2, %0;" : "+l"(acc) : "l"(a), "l"(b));
}
__global__ void __launch_bounds__(128) qproj_kernel(
    const float* __restrict__ V, const float* __restrict__ W,
    const float* __restrict__ bias, const int* __restrict__ rows, int n_rows)
{
    __shared__ float vsh[D][8];
    const int t = threadIdx.x;
    const int row0 = blockIdx.x * 8;
    #pragma unroll
    for (int r = 0; r < 8; r++) {
        int row = row0 + r; if (row >= n_rows) row = n_rows - 1;
        vsh[t][r] = V[(size_t)rows[row] * D + t];
    }
    __syncthreads();
    u64 acc[4] = {0ull, 0ull, 0ull, 0ull};
    #pragma unroll 4
    for (int e = 0; e < D; e++) {
        float w = W[e * D + t];
        u64 wp = pack2(w, w);
        ulonglong2 p0 = *(const ulonglong2*)&vsh[e][0];
        ulonglong2 p1 = *(const ulonglong2*)&vsh[e][4];
        fma2(acc[0], p0.x, wp); fma2(acc[1], p0.y, wp);
        fma2(acc[2], p1.x, wp); fma2(acc[3], p1.y, wp);
    }
    float bb = bias[t];
    #pragma unroll
    for (int rp = 0; rp < 4; rp++) {
        float x, y; unpack2(acc[rp], x, y);
        int r0 = row0 + 2 * rp, r1 = r0 + 1;
        if (r0 < n_rows) g_Q[(size_t)r0 * D + t] = x + bb;
        if (r1 < n_rows) g_Q[(size_t)r1 * D + t] = y + bb;
    }
}

// ---------------- P projection: P = V @ W1a (bf16 3-pass, as R5) ---------------
__global__ void __launch_bounds__(256, 2) pproj_kernel(const float* __restrict__ V,
                                                       int n_videos, int n_tiles)
{
    extern __shared__ char smc[];
    u32 sb = smem_u32(smc);
    const int t = threadIdx.x, w = t >> 5, lane = t & 31;
    const int mw = w >> 1, nw = w & 1;
    const int r = t >> 2, cc = t & 3;

    {   // stage B (bf16 hi|lo, 64KB)
        const float4* src = (const float4*)g_Bimg;
        float4* dst = (float4*)(smc + PP_B);
        #pragma unroll
        for (int i = 0; i < 16; i++) dst[t + 256 * i] = src[t + 256 * i];
    }
    const float4* V4 = (const float4*)V;

    for (int tile = blockIdx.x; tile < n_tiles; tile += gridDim.x) {
        __syncthreads();
        {
            int gr = tile * 64 + r; if (gr >= n_videos) gr = n_videos - 1;
            const float4* Vr = V4 + (size_t)gr * 32;
            #pragma unroll
            for (int m = 0; m < 4; m++) {
                int j = cc + 4 * m;
                float4 f0 = Vr[2 * j], f1 = Vr[2 * j + 1];
                uint2 hA, lA, hB, lB; split4(f0, hA, lA); split4(f1, hB, lB);
                u32 off = (u32)(r * 256 + ((j ^ (r & 7)) << 4));
                *(uint4*)(smc + PP_A + off)         = make_uint4(hA.x, hA.y, hB.x, hB.y);
                *(uint4*)(smc + PP_A + 16384 + off) = make_uint4(lA.x, lA.y, lB.x, lB.y);
            }
        }
        __syncthreads();

        float acc[8][4];
        #pragma unroll
        for (int a = 0; a < 8; a++) { acc[a][0]=0.f; acc[a][1]=0.f; acc[a][2]=0.f; acc[a][3]=0.f; }
        gemm16(sb + PP_A, sb + PP_B, lane, mw, nw, acc);

        #pragma unroll
        for (int nt = 0; nt < 8; nt++) {
            int gr0 = tile * 64 + 16 * mw + (lane >> 2);
            int gc = 64 * nw + 8 * nt + 2 * (lane & 3);
            if (gr0 < n_videos)
                *(float2*)&g_P[(size_t)gr0 * D + gc] = make_float2(acc[nt][0], acc[nt][1]);
            if (gr0 + 8 < n_videos)
                *(float2*)&g_P[(size_t)(gr0 + 8) * D + gc] = make_float2(acc[nt][2], acc[nt][3]);
        }
    }
}

// ---------------- agg: M=128 tile (4 nodes), fp16 2-pass HMMA ------------------
__global__ void __launch_bounds__(256, 2) agg_kernel(
    const float* __restrict__ V, const int* __restrict__ neigh,
    const float* __restrict__ b2, const float* __restrict__ W3,
    float* __restrict__ out, int n_nodes, int n_tiles)
{
    extern __shared__ char smc[];
    u32 sb = smem_u32(smc);
    const int t = threadIdx.x, w = t >> 5, lane = t & 31;
    const int mw = w >> 1, nw = w & 1;

    float2* b2w3  = (float2*)(smc + AG_BW);
    float4* qst4  = (float4*)(smc + AG_QST);   // [2buf][128]
    int*    idx_s = (int*)(smc + AG_IDX);      // [2buf][128]
    float*  spart = (float*)(smc + AG_SP);     // [2][128]
    float*  att   = (float*)(smc + AG_ATT);    // [128]
    float4* pp4   = (float4*)(smc + AG_A);     // partials overlay (post-GEMM)

    {   // stage B (fp16 single, 32KB)
        const float4* src = (const float4*)g_W2h;
        float4* dst = (float4*)(smc + AG_B);
        #pragma unroll
        for (int i = 0; i < 8; i++) dst[t + 256 * i] = src[t + 256 * i];
    }
    if (t < D) b2w3[t] = make_float2(b2[t], W3[t]);

    const float4* P4 = (const float4*)g_P;
    const float4* Q4 = (const float4*)g_Q;
    const float4* V4 = (const float4*)V;
    const int idx_max = n_nodes * 32 - 1;

    // prologue: idx + Q for first tile into buffer 0
    {
        int tile0 = blockIdx.x; if (tile0 >= n_tiles) tile0 = n_tiles - 1;
        if (t < 128) {
            int gi = tile0 * 128 + t; if (gi > idx_max) gi = idx_max;
            idx_s[t] = neigh[gi];
            int qr = 4 * tile0 + (t >> 5); if (qr >= n_nodes) qr = n_nodes - 1;
            qst4[t] = Q4[(size_t)qr * 32 + (t & 31)];
        }
    }
    __syncthreads();
    int bp = 0;

    for (int tile = blockIdx.x; tile < n_tiles; tile += gridDim.x) {
        const int cur = bp, nxt = bp ^ 1;

        // convert: A = split_f16(relu(P[vid] + Q[node])), 128 rows
        {
            const int rr = t >> 2, cc4 = t & 3;
            #pragma unroll
            for (int h = 0; h < 2; h++) {
                int r = 64 * h + rr;
                int vid = idx_s[cur * 128 + r];
                const float4* Pr = P4 + (size_t)vid * 32;
                const float4* Qr = qst4 + cur * 128 + (r >> 5) * 32;
                #pragma unroll
                for (int m = 0; m < 4; m++) {
                    int j = cc4 + 4 * m;
                    float4 p0 = Pr[2 * j], p1 = Pr[2 * j + 1];
                    float4 q0 = Qr[2 * j], q1 = Qr[2 * j + 1];
                    float4 h0, h1;
                    h0.x = fmaxf(p0.x + q0.x, 0.f); h0.y = fmaxf(p0.y + q0.y, 0.f);
                    h0.z = fmaxf(p0.z + q0.z, 0.f); h0.w = fmaxf(p0.w + q0.w, 0.f);
                    h1.x = fmaxf(p1.x + q1.x, 0.f); h1.y = fmaxf(p1.y + q1.y, 0.f);
                    h1.z = fmaxf(p1.z + q1.z, 0.f); h1.w = fmaxf(p1.w + q1.w, 0.f);
                    uint2 hA, lA, hB, lB; split4h(h0, hA, lA); split4h(h1, hB, lB);
                    u32 off = (u32)(r * 256 + ((j ^ (r & 7)) << 4));
                    *(uint4*)(smc + AG_A + off)         = make_uint4(hA.x, hA.y, hB.x, hB.y);
                    *(uint4*)(smc + AG_A + 32768 + off) = make_uint4(lA.x, lA.y, lB.x, lB.y);
                }
            }
        }
        __syncthreads();

        // prefetch next tile's idx + Q (hidden by GEMM)
        int tnext = tile + gridDim.x; if (tnext >= n_tiles) tnext = tile;
        if (t < 128) {
            int gi = tnext * 128 + t; if (gi > idx_max) gi = idx_max;
            idx_s[nxt * 128 + t] = neigh[gi];
            int qr = 4 * tnext + (t >> 5); if (qr >= n_nodes) qr = n_nodes - 1;
            qst4[nxt * 128 + t] = Q4[(size_t)qr * 32 + (t & 31)];
        }

        float acc[2][8][4];
        #pragma unroll
        for (int a = 0; a < 2; a++)
            #pragma unroll
            for (int b = 0; b < 8; b++)
                #pragma unroll
                for (int c = 0; c < 4; c++) acc[a][b][c] = 0.f;
        gemm32_f16(sb + AG_A, sb + AG_B, lane, mw, nw, acc);

        // scores: s[row] = sum_c relu(h2 + b2) * W3
        #pragma unroll
        for (int mt = 0; mt < 2; mt++) {
            float sp0 = 0.f, sp1 = 0.f;
            #pragma unroll
            for (int nt = 0; nt < 8; nt++) {
                int gc = 64 * nw + 8 * nt + 2 * (lane & 3);
                float2 bw0 = b2w3[gc], bw1 = b2w3[gc + 1];
                sp0 += fmaxf(acc[mt][nt][0] + bw0.x, 0.f) * bw0.y + fmaxf(acc[mt][nt][1] + bw1.x, 0.f) * bw1.y;
                sp1 += fmaxf(acc[mt][nt][2] + bw0.x, 0.f) * bw0.y + fmaxf(acc[mt][nt][3] + bw1.x, 0.f) * bw1.y;
            }
            sp0 += __shfl_xor_sync(0xffffffffu, sp0, 1); sp0 += __shfl_xor_sync(0xffffffffu, sp0, 2);
            sp1 += __shfl_xor_sync(0xffffffffu, sp1, 1); sp1 += __shfl_xor_sync(0xffffffffu, sp1, 2);
            if ((lane & 3) == 0) {
                spart[nw * 128 + 32 * mw + 16 * mt + (lane >> 2)]     = sp0;
                spart[nw * 128 + 32 * mw + 16 * mt + 8 + (lane >> 2)] = sp1;
            }
        }
        __syncthreads();                       // spart ready; GEMM done (A reusable)

        if (w < 4) {                           // softmax: warp w = node-local w
            float s = spart[32 * w + lane] + spart[128 + 32 * w + lane];
            float m = s;
            #pragma unroll
            for (int o = 16; o > 0; o >>= 1) m = fmaxf(m, __shfl_xor_sync(0xffffffffu, m, o));
            float ev = expf(s - m);
            float sum = ev;
            #pragma unroll
            for (int o = 16; o > 0; o >>= 1) sum += __shfl_xor_sync(0xffffffffu, sum, o);
            att[32 * w + lane] = ev / sum;
        }
        __syncthreads();

        // aggregate: thread = (node, k-half, col4); partials into A overlay
        {
            int nd = t >> 6, kh = (t >> 5) & 1, c4 = t & 31;
            float4 a4 = make_float4(0.f, 0.f, 0.f, 0.f);
            #pragma unroll
            for (int kk = 0; kk < 16; kk++) {
                int k = 32 * nd + 16 * kh + kk;
                float a = att[k];
                int vid = idx_s[cur * 128 + k];
                float4 v = V4[(size_t)vid * 32 + c4];
                a4.x = fmaf(a, v.x, a4.x); a4.y = fmaf(a, v.y, a4.y);
                a4.z = fmaf(a, v.z, a4.z); a4.w = fmaf(a, v.w, a4.w);
            }
            pp4[(nd * 2 + kh) * 32 + c4] = a4;
        }
        __syncthreads();
        if (t < 128) {
            int nd = t >> 5, c4 = t & 31;
            float4 s0 = pp4[(nd * 2) * 32 + c4];
            float4 s1 = pp4[(nd * 2 + 1) * 32 + c4];
            float4 rr = make_float4(s0.x + s1.x, s0.y + s1.y, s0.z + s1.z, s0.w + s1.w);
            int ng = 4 * tile + nd;
            if (ng < n_nodes) ((float4*)out)[(size_t)ng * 32 + c4] = rr;
        }
        __syncthreads();                       // pp4 reads done before next convert

        bp ^= 1;
    }
}

// -------------------------------------------------------------------------------
extern "C" void kernel_launch(void* const* d_in, const int* in_sizes, int n_in,
                              void* d_out, int out_size)
{
    const float* V     = (const float*)d_in[0];
    const int*   nodes = (const int*)  d_in[1];
    const int*   neigh = (const int*)  d_in[2];
    const float* W1    = (const float*)d_in[3];
    const float* b1    = (const float*)d_in[4];
    const float* W2    = (const float*)d_in[5];
    const float* b2    = (const float*)d_in[6];
    const float* W3    = (const float*)d_in[7];
    float* out = (float*)d_out;

    const int n_videos = in_sizes[0] / D;
    const int n_nodes  = in_sizes[1];
    const int p_tiles  = (n_videos + 63) / 64;
    const int a_tiles  = (n_nodes + 3) / 4;

    cudaFuncSetAttribute(pproj_kernel, cudaFuncAttributeMaxDynamicSharedMemorySize, PP_SMEM);
    cudaFuncSetAttribute(agg_kernel,   cudaFuncAttributeMaxDynamicSharedMemorySize, AG_SMEM);

    prep_kernel<<<2, 128>>>(W1, W2);
    qproj_kernel<<<(n_nodes + 7) / 8, 128>>>(V, W1 + D * D, b1, nodes, n_nodes);
    pproj_kernel<<<296, 256, PP_SMEM>>>(V, n_videos, p_tiles);
    agg_kernel<<<296, 256, AG_SMEM>>>(V, neigh, b2, W3, out, n_nodes, a_tiles);
}

// round 7
// speedup vs baseline: 3.8470x; 1.1559x over previous
#include <cuda_runtime.h>
#include <cuda_bf16.h>
#include <cuda_fp16.h>
#include <cstdint>

#define D 128
#define NV_MAX 200000
#define NN_MAX 20000

typedef unsigned long long u64;
typedef unsigned int u32;

// ---------------- device scratch (no allocs allowed) ------------------------
__device__ float g_P[(size_t)NV_MAX * D];             // V @ W1a (fp32)
__device__ float g_Q[(size_t)NN_MAX * D];             // V[nodes] @ W1b + b1
__device__ __align__(16) unsigned char g_W1a_h[32768]; // W1a^T fp16, swizzled
__device__ __align__(16) unsigned char g_W1b_h[32768]; // W1b^T fp16, swizzled
__device__ __align__(16) unsigned char g_W2h[32768];   // W2^T  fp16, swizzled

// ---------------- smem layouts ------------------------------------------------
// proj kernel (96 KB -> 2 CTAs/SM)
#define PP_B    0
#define PP_A    32768      // A hi 32K | lo 32K
#define PP_SMEM 98304
// agg kernel (~104 KB -> 2 CTAs/SM)
#define AG_B    0          // B fp16 32K
#define AG_A    32768      // A fp16 hi 32K | lo 32K (overlay: agg partials)
#define AG_BW   98304      // float2 b2/W3 [128]          (1K)
#define AG_QST  99328      // float4 q rows [2buf][128]   (4K)
#define AG_IDX  103424     // int [2buf][128]             (1K)
#define AG_SP   104448     // score partials float[2][128](1K)
#define AG_ATT  105472     // att float[128]              (512B)
#define AG_SMEM 106496

// ---------------- helpers ------------------------------------------------------
__device__ __forceinline__ u32 smem_u32(const void* p) {
    u32 a; asm("{ .reg .u64 t; cvta.to.shared.u64 t, %1; cvt.u32.u64 %0, t; }" : "=r"(a) : "l"(p));
    return a;
}
__device__ __forceinline__ void ldm_x4(u32 addr, u32* r) {
    asm volatile("ldmatrix.sync.aligned.m8n8.x4.shared.b16 {%0,%1,%2,%3}, [%4];"
        : "=r"(r[0]), "=r"(r[1]), "=r"(r[2]), "=r"(r[3]) : "r"(addr));
}
__device__ __forceinline__ void mma_f16(float* c, const u32* a, const u32* b) {
    asm volatile("mma.sync.aligned.m16n8k16.row.col.f32.f16.f16.f32 "
        "{%0,%1,%2,%3}, {%4,%5,%6,%7}, {%8,%9}, {%0,%1,%2,%3};"
        : "+f"(c[0]), "+f"(c[1]), "+f"(c[2]), "+f"(c[3])
        : "r"(a[0]), "r"(a[1]), "r"(a[2]), "r"(a[3]), "r"(b[0]), "r"(b[1]));
}
// fp16 split: hi = f16(x), lo = f16(x - hi)
__device__ __forceinline__ void split4h(float4 v, uint2& hi, uint2& lo) {
    __half2 h01 = __floats2half2_rn(v.x, v.y);
    __half2 h23 = __floats2half2_rn(v.z, v.w);
    float rx = v.x - __half2float(__low2half(h01));
    float ry = v.y - __half2float(__high2half(h01));
    float rz = v.z - __half2float(__low2half(h23));
    float rw = v.w - __half2float(__high2half(h23));
    __half2 l01 = __floats2half2_rn(rx, ry);
    __half2 l23 = __floats2half2_rn(rz, rw);
    hi = make_uint2(*(u32*)&h01, *(u32*)&h23);
    lo = make_uint2(*(u32*)&l01, *(u32*)&l23);
}

// ---------------- GEMM: block 128x128, warp 32x64, fp16 2-pass, ks range -------
template<int KS0, int KS1>
__device__ __forceinline__ void gemm32_rng(u32 sA, u32 sB, int lane, int mw, int nw,
                                           float (&acc)[2][8][4]) {
    const int lr   = lane & 7;
    const int akl  = lane >> 4;
    const int arow = lr + ((lane >> 3) & 1) * 8;
    const int bkl  = (lane >> 3) & 1;
    const int brow = lr + (lane >> 4) * 8;
    u32 aoffm[2];
    #pragma unroll
    for (int mt = 0; mt < 2; mt++) aoffm[mt] = (u32)((32 * mw + 16 * mt + arow) * 256);
    u32 boff[4];
    #pragma unroll
    for (int n2 = 0; n2 < 4; n2++) boff[n2] = (u32)((64 * nw + 16 * n2 + brow) * 256);

    #pragma unroll 1
    for (int ks = KS0; ks < KS1; ks++) {
        const int kc0 = ks * 2;
        const u32 axor = (u32)(((kc0 + akl) ^ lr) << 4);
        const u32 bxor = (u32)(((kc0 + bkl) ^ lr) << 4);
        u32 ah[2][4], al[2][4], b[4][4];
        #pragma unroll
        for (int mt = 0; mt < 2; mt++) {
            ldm_x4(sA + aoffm[mt] + axor, ah[mt]);
            ldm_x4(sA + 32768 + aoffm[mt] + axor, al[mt]);
        }
        #pragma unroll
        for (int n2 = 0; n2 < 4; n2++) ldm_x4(sB + boff[n2] + bxor, b[n2]);
        #pragma unroll
        for (int mt = 0; mt < 2; mt++)
            #pragma unroll
            for (int nt = 0; nt < 8; nt++) {
                mma_f16(acc[mt][nt], ah[mt], &b[nt >> 1][(nt & 1) * 2]);
                mma_f16(acc[mt][nt], al[mt], &b[nt >> 1][(nt & 1) * 2]);
            }
    }
}

// ---------------- prep: weights -> transposed fp16 swizzled images -------------
__global__ void prep_kernel(const float* __restrict__ W1, const float* __restrict__ W2) {
    int n = threadIdx.x;
    const float* W = (blockIdx.x == 0) ? W1 : (blockIdx.x == 1) ? (W1 + D * D) : W2;
    unsigned char* img = (blockIdx.x == 0) ? g_W1a_h : (blockIdx.x == 1) ? g_W1b_h : g_W2h;
    for (int k = 0; k < D; k++) {
        __half h = __float2half_rn(W[k * D + n]);
        int o = n * 256 + ((((k >> 3) ^ (n & 7))) << 4) + ((k & 7) << 1);
        *(__half*)(img + o) = h;
    }
}

// ---------------- proj: dst = src_rows @ Wimg (+bias), fp16 2-pass, M=128 ------
// mode 0: P = V @ W1a            (no gather, no bias, dst g_P)
// mode 1: Q = V[nodes] @ W1b + b1 (gather,  bias b1,  dst g_Q)
__global__ void __launch_bounds__(256, 2) proj_kernel(
    const float* __restrict__ V, const int* __restrict__ gidx,
    const float* __restrict__ bias, int n_rows, int n_tiles, int mode)
{
    extern __shared__ char smc[];
    u32 sb = smem_u32(smc);
    const int t = threadIdx.x, w = t >> 5, lane = t & 31;
    const int mw = w >> 1, nw = w & 1;
    const int rr = t >> 2, cc4 = t & 3;

    {   // stage B (fp16, 32KB)
        const float4* src = (const float4*)(mode ? g_W1b_h : g_W1a_h);
        float4* dst = (float4*)(smc + PP_B);
        #pragma unroll
        for (int i = 0; i < 8; i++) dst[t + 256 * i] = src[t + 256 * i];
    }
    float* dstP = mode ? g_Q : g_P;
    const float4* V4 = (const float4*)V;

    for (int tile = blockIdx.x; tile < n_tiles; tile += gridDim.x) {
        __syncthreads();
        // convert 128 rows -> A hi/lo
        #pragma unroll
        for (int h = 0; h < 2; h++) {
            int r = 64 * h + rr;
            int gr = tile * 128 + r; if (gr >= n_rows) gr = n_rows - 1;
            int src = mode ? gidx[gr] : gr;
            const float4* Vr = V4 + (size_t)src * 32;
            #pragma unroll
            for (int m = 0; m < 4; m++) {
                int j = cc4 + 4 * m;
                float4 f0 = Vr[2 * j], f1 = Vr[2 * j + 1];
                uint2 hA, lA, hB, lB; split4h(f0, hA, lA); split4h(f1, hB, lB);
                u32 off = (u32)(r * 256 + ((j ^ (r & 7)) << 4));
                *(uint4*)(smc + PP_A + off)         = make_uint4(hA.x, hA.y, hB.x, hB.y);
                *(uint4*)(smc + PP_A + 32768 + off) = make_uint4(lA.x, lA.y, lB.x, lB.y);
            }
        }
        __syncthreads();

        float acc[2][8][4];
        #pragma unroll
        for (int a = 0; a < 2; a++)
            #pragma unroll
            for (int b = 0; b < 8; b++)
                #pragma unroll
                for (int c = 0; c < 4; c++) acc[a][b][c] = 0.f;
        gemm32_rng<0, 8>(sb + PP_A, sb + PP_B, lane, mw, nw, acc);

        #pragma unroll
        for (int mt = 0; mt < 2; mt++)
            #pragma unroll
            for (int nt = 0; nt < 8; nt++) {
                int gr0 = tile * 128 + 32 * mw + 16 * mt + (lane >> 2);
                int gc = 64 * nw + 8 * nt + 2 * (lane & 3);
                float bx = 0.f, by = 0.f;
                if (mode) { bx = bias[gc]; by = bias[gc + 1]; }
                if (gr0 < n_rows)
                    *(float2*)&dstP[(size_t)gr0 * D + gc] =
                        make_float2(acc[mt][nt][0] + bx, acc[mt][nt][1] + by);
                if (gr0 + 8 < n_rows)
                    *(float2*)&dstP[(size_t)(gr0 + 8) * D + gc] =
                        make_float2(acc[mt][nt][2] + bx, acc[mt][nt][3] + by);
            }
    }
}

// ---------------- agg: M=128 (4 nodes), fp16 2-pass, k-split pipelined ---------
__global__ void __launch_bounds__(256, 2) agg_kernel(
    const float* __restrict__ V, const int* __restrict__ neigh,
    const float* __restrict__ b2, const float* __restrict__ W3,
    float* __restrict__ out, int n_nodes, int n_tiles)
{
    extern __shared__ char smc[];
    u32 sb = smem_u32(smc);
    const int t = threadIdx.x, w = t >> 5, lane = t & 31;
    const int mw = w >> 1, nw = w & 1;
    const int rr = t >> 2, cc4 = t & 3;

    float2* b2w3  = (float2*)(smc + AG_BW);
    float4* qst4  = (float4*)(smc + AG_QST);   // [2buf][128]
    int*    idx_s = (int*)(smc + AG_IDX);      // [2buf][128]
    float*  spart = (float*)(smc + AG_SP);     // [2][128]
    float*  att   = (float*)(smc + AG_ATT);    // [128]
    float4* pp4   = (float4*)(smc + AG_A);     // partials overlay (post-GEMM)

    {   // stage B (fp16, 32KB)
        const float4* src = (const float4*)g_W2h;
        float4* dst = (float4*)(smc + AG_B);
        #pragma unroll
        for (int i = 0; i < 8; i++) dst[t + 256 * i] = src[t + 256 * i];
    }
    if (t < D) b2w3[t] = make_float2(b2[t], W3[t]);

    const float4* P4 = (const float4*)g_P;
    const float4* Q4 = (const float4*)g_Q;
    const float4* V4 = (const float4*)V;
    const int idx_max = n_nodes * 32 - 1;

    // prologue: idx + Q for first tile into buffer 0
    {
        int tile0 = blockIdx.x; if (tile0 >= n_tiles) tile0 = n_tiles - 1;
        if (t < 128) {
            int gi = tile0 * 128 + t; if (gi > idx_max) gi = idx_max;
            idx_s[t] = neigh[gi];
            int qr = 4 * tile0 + (t >> 5); if (qr >= n_nodes) qr = n_nodes - 1;
            qst4[t] = Q4[(size_t)qr * 32 + (t & 31)];
        }
    }
    __syncthreads();
    int bp = 0;

    for (int tile = blockIdx.x; tile < n_tiles; tile += gridDim.x) {
        const int cur = bp, nxt = bp ^ 1;

        // ---- load all P float4s for this thread's 2 rows into registers ----
        float4 preg[2][8];
        #pragma unroll
        for (int h = 0; h < 2; h++) {
            int r = 64 * h + rr;
            int vid = idx_s[cur * 128 + r];
            const float4* Pr = P4 + (size_t)vid * 32;
            #pragma unroll
            for (int m = 0; m < 4; m++) {
                int j = cc4 + 4 * m;
                preg[h][2 * m]     = Pr[2 * j];
                preg[h][2 * m + 1] = Pr[2 * j + 1];
            }
        }
        // ---- phase 1 convert: k < 64 (m = 0,1) ----
        #pragma unroll
        for (int h = 0; h < 2; h++) {
            int r = 64 * h + rr;
            const float4* Qr = qst4 + cur * 128 + (r >> 5) * 32;
            #pragma unroll
            for (int m = 0; m < 2; m++) {
                int j = cc4 + 4 * m;
                float4 p0 = preg[h][2 * m], p1 = preg[h][2 * m + 1];
                float4 q0 = Qr[2 * j], q1 = Qr[2 * j + 1];
                float4 h0, h1;
                h0.x = fmaxf(p0.x + q0.x, 0.f); h0.y = fmaxf(p0.y + q0.y, 0.f);
                h0.z = fmaxf(p0.z + q0.z, 0.f); h0.w = fmaxf(p0.w + q0.w, 0.f);
                h1.x = fmaxf(p1.x + q1.x, 0.f); h1.y = fmaxf(p1.y + q1.y, 0.f);
                h1.z = fmaxf(p1.z + q1.z, 0.f); h1.w = fmaxf(p1.w + q1.w, 0.f);
                uint2 hA, lA, hB, lB; split4h(h0, hA, lA); split4h(h1, hB, lB);
                u32 off = (u32)(r * 256 + ((j ^ (r & 7)) << 4));
                *(uint4*)(smc + AG_A + off)         = make_uint4(hA.x, hA.y, hB.x, hB.y);
                *(uint4*)(smc + AG_A + 32768 + off) = make_uint4(lA.x, lA.y, lB.x, lB.y);
            }
        }
        __syncthreads();   // bar1: A[k<64] ready

        // prefetch next tile's idx + Q (hidden by phase2 + GEMM)
        int tnext = tile + gridDim.x; if (tnext >= n_tiles) tnext = tile;
        if (t < 128) {
            int gi = tnext * 128 + t; if (gi > idx_max) gi = idx_max;
            idx_s[nxt * 128 + t] = neigh[gi];
            int qr = 4 * tnext + (t >> 5); if (qr >= n_nodes) qr = n_nodes - 1;
            qst4[nxt * 128 + t] = Q4[(size_t)qr * 32 + (t & 31)];
        }

        // ---- phase 2 convert: k >= 64 (m = 2,3), then GEMM ks 0..3 ----
        #pragma unroll
        for (int h = 0; h < 2; h++) {
            int r = 64 * h + rr;
            const float4* Qr = qst4 + cur * 128 + (r >> 5) * 32;
            #pragma unroll
            for (int m = 2; m < 4; m++) {
                int j = cc4 + 4 * m;
                float4 p0 = preg[h][2 * m], p1 = preg[h][2 * m + 1];
                float4 q0 = Qr[2 * j], q1 = Qr[2 * j + 1];
                float4 h0, h1;
                h0.x = fmaxf(p0.x + q0.x, 0.f); h0.y = fmaxf(p0.y + q0.y, 0.f);
                h0.z = fmaxf(p0.z + q0.z, 0.f); h0.w = fmaxf(p0.w + q0.w, 0.f);
                h1.x = fmaxf(p1.x + q1.x, 0.f); h1.y = fmaxf(p1.y + q1.y, 0.f);
                h1.z = fmaxf(p1.z + q1.z, 0.f); h1.w = fmaxf(p1.w + q1.w, 0.f);
                uint2 hA, lA, hB, lB; split4h(h0, hA, lA); split4h(h1, hB, lB);
                u32 off = (u32)(r * 256 + ((j ^ (r & 7)) << 4));
                *(uint4*)(smc + AG_A + off)         = make_uint4(hA.x, hA.y, hB.x, hB.y);
                *(uint4*)(smc + AG_A + 32768 + off) = make_uint4(lA.x, lA.y, lB.x, lB.y);
            }
        }

        float acc[2][8][4];
        #pragma unroll
        for (int a = 0; a < 2; a++)
            #pragma unroll
            for (int b = 0; b < 8; b++)
                #pragma unroll
                for (int c = 0; c < 4; c++) acc[a][b][c] = 0.f;
        gemm32_rng<0, 4>(sb + AG_A, sb + AG_B, lane, mw, nw, acc);
        __syncthreads();   // bar2: A[k>=64] ready
        gemm32_rng<4, 8>(sb + AG_A, sb + AG_B, lane, mw, nw, acc);

        // scores: s[row] = sum_c relu(h2 + b2) * W3
        #pragma unroll
        for (int mt = 0; mt < 2; mt++) {
            float sp0 = 0.f, sp1 = 0.f;
            #pragma unroll
            for (int nt = 0; nt < 8; nt++) {
                int gc = 64 * nw + 8 * nt + 2 * (lane & 3);
                float2 bw0 = b2w3[gc], bw1 = b2w3[gc + 1];
                sp0 += fmaxf(acc[mt][nt][0] + bw0.x, 0.f) * bw0.y + fmaxf(acc[mt][nt][1] + bw1.x, 0.f) * bw1.y;
                sp1 += fmaxf(acc[mt][nt][2] + bw0.x, 0.f) * bw0.y + fmaxf(acc[mt][nt][3] + bw1.x, 0.f) * bw1.y;
            }
            sp0 += __shfl_xor_sync(0xffffffffu, sp0, 1); sp0 += __shfl_xor_sync(0xffffffffu, sp0, 2);
            sp1 += __shfl_xor_sync(0xffffffffu, sp1, 1); sp1 += __shfl_xor_sync(0xffffffffu, sp1, 2);
            if ((lane & 3) == 0) {
                spart[nw * 128 + 32 * mw + 16 * mt + (lane >> 2)]     = sp0;
                spart[nw * 128 + 32 * mw + 16 * mt + 8 + (lane >> 2)] = sp1;
            }
        }
        __syncthreads();   // spart ready; GEMM done (A reusable)

        if (w < 4) {       // softmax: warp w = node-local w
            float s = spart[32 * w + lane] + spart[128 + 32 * w + lane];
            float m = s;
            #pragma unroll
            for (int o = 16; o > 0; o >>= 1) m = fmaxf(m, __shfl_xor_sync(0xffffffffu, m, o));
            float ev = expf(s - m);
            float sum = ev;
            #pragma unroll
            for (int o = 16; o > 0; o >>= 1) sum += __shfl_xor_sync(0xffffffffu, sum, o);
            att[32 * w + lane] = ev / sum;
        }
        __syncthreads();

        // aggregate: thread = (node, k-half, col4); partials into A overlay
        {
            int nd = t >> 6, kh = (t >> 5) & 1, c4 = t & 31;
            float4 a4 = make_float4(0.f, 0.f, 0.f, 0.f);
            #pragma unroll
            for (int kk = 0; kk < 16; kk++) {
                int k = 32 * nd + 16 * kh + kk;
                float a = att[k];
                int vid = idx_s[cur * 128 + k];
                float4 v = V4[(size_t)vid * 32 + c4];
                a4.x = fmaf(a, v.x, a4.x); a4.y = fmaf(a, v.y, a4.y);
                a4.z = fmaf(a, v.z, a4.z); a4.w = fmaf(a, v.w, a4.w);
            }
            pp4[(nd * 2 + kh) * 32 + c4] = a4;
        }
        __syncthreads();
        if (t < 128) {
            int nd = t >> 5, c4 = t & 31;
            float4 s0 = pp4[(nd * 2) * 32 + c4];
            float4 s1 = pp4[(nd * 2 + 1) * 32 + c4];
            float4 rv = make_float4(s0.x + s1.x, s0.y + s1.y, s0.z + s1.z, s0.w + s1.w);
            int ng = 4 * tile + nd;
            if (ng < n_nodes) ((float4*)out)[(size_t)ng * 32 + c4] = rv;
        }
        __syncthreads();   // pp4 reads done before next convert

        bp ^= 1;
    }
}

// -------------------------------------------------------------------------------
extern "C" void kernel_launch(void* const* d_in, const int* in_sizes, int n_in,
                              void* d_out, int out_size)
{
    const float* V     = (const float*)d_in[0];
    const int*   nodes = (const int*)  d_in[1];
    const int*   neigh = (const int*)  d_in[2];
    const float* W1    = (const float*)d_in[3];
    const float* b1    = (const float*)d_in[4];
    const float* W2    = (const float*)d_in[5];
    const float* b2    = (const float*)d_in[6];
    const float* W3    = (const float*)d_in[7];
    float* out = (float*)d_out;

    const int n_videos = in_sizes[0] / D;
    const int n_nodes  = in_sizes[1];
    const int p_tiles  = (n_videos + 127) / 128;
    const int q_tiles  = (n_nodes + 127) / 128;
    const int a_tiles  = (n_nodes + 3) / 4;

    cudaFuncSetAttribute(proj_kernel, cudaFuncAttributeMaxDynamicSharedMemorySize, PP_SMEM);
    cudaFuncSetAttribute(agg_kernel,  cudaFuncAttributeMaxDynamicSharedMemorySize, AG_SMEM);

    prep_kernel<<<3, 128>>>(W1, W2);
    proj_kernel<<<296, 256, PP_SMEM>>>(V, nullptr, nullptr, n_videos, p_tiles, 0);
    proj_kernel<<<q_tiles, 256, PP_SMEM>>>(V, nodes, b1, n_nodes, q_tiles, 1);
    agg_kernel<<<296, 256, AG_SMEM>>>(V, neigh, b2, W3, out, n_nodes, a_tiles);
}

// round 8
// speedup vs baseline: 5.4583x; 1.4188x over previous
#include <cuda_runtime.h>
#include <cuda_fp16.h>
#include <cstdint>

#define D 128
#define NV_MAX 200000
#define NN_MAX 20000

typedef unsigned long long u64;
typedef unsigned int u32;

// ---------------- device scratch (no allocs allowed) ------------------------
__device__ float g_P[(size_t)NV_MAX * D];              // V @ W1a (fp32)
__device__ float g_Q[(size_t)NN_MAX * D];              // V[nodes] @ W1b + b1
__device__ __align__(16) unsigned char g_W1a_h[32768]; // W1a^T fp16, swizzled
__device__ __align__(16) unsigned char g_W1b_h[32768]; // W1b^T fp16, swizzled
__device__ __align__(16) unsigned char g_W2h[32768];   // W2^T  fp16, swizzled

// ---------------- smem layouts ------------------------------------------------
// proj kernel (64 KB + pad)
#define PP_B    0
#define PP_A    32768
#define PP_SMEM 66560
// agg kernel (~72 KB -> 2 CTAs/SM easily)
#define AG_B    0          // B fp16 32K
#define AG_A    32768      // A fp16 32K (overlay: agg partials post-GEMM)
#define AG_BW   65536      // float2 b2/W3 [128]          (1K)
#define AG_QST  66560      // float4 q rows [2buf][128]   (4K)
#define AG_IDX  70656      // int [2buf][128]             (1K)
#define AG_SP   71680      // score partials float[2][128](1K)
#define AG_ATT  72704      // att float[128]              (512B)
#define AG_SMEM 73728

// ---------------- helpers ------------------------------------------------------
__device__ __forceinline__ u32 smem_u32(const void* p) {
    u32 a; asm("{ .reg .u64 t; cvta.to.shared.u64 t, %1; cvt.u32.u64 %0, t; }" : "=r"(a) : "l"(p));
    return a;
}
__device__ __forceinline__ void ldm_x4(u32 addr, u32* r) {
    asm volatile("ldmatrix.sync.aligned.m8n8.x4.shared.b16 {%0,%1,%2,%3}, [%4];"
        : "=r"(r[0]), "=r"(r[1]), "=r"(r[2]), "=r"(r[3]) : "r"(addr));
}
__device__ __forceinline__ void mma_f16(float* c, const u32* a, const u32* b) {
    asm volatile("mma.sync.aligned.m16n8k16.row.col.f32.f16.f16.f32 "
        "{%0,%1,%2,%3}, {%4,%5,%6,%7}, {%8,%9}, {%0,%1,%2,%3};"
        : "+f"(c[0]), "+f"(c[1]), "+f"(c[2]), "+f"(c[3])
        : "r"(a[0]), "r"(a[1]), "r"(a[2]), "r"(a[3]), "r"(b[0]), "r"(b[1]));
}
// fp16 pack (single precision pass): 2x float4 -> uint4 of half2
__device__ __forceinline__ uint4 pack8h(float4 a, float4 b) {
    __half2 h0 = __floats2half2_rn(a.x, a.y);
    __half2 h1 = __floats2half2_rn(a.z, a.w);
    __half2 h2 = __floats2half2_rn(b.x, b.y);
    __half2 h3 = __floats2half2_rn(b.z, b.w);
    return make_uint4(*(u32*)&h0, *(u32*)&h1, *(u32*)&h2, *(u32*)&h3);
}

// ---------------- GEMM: block 128x128, warp 32x64, fp16 single-pass ------------
__device__ __forceinline__ void gemm32_1p(u32 sA, u32 sB, int lane, int mw, int nw,
                                          float (&acc)[2][8][4]) {
    const int lr   = lane & 7;
    const int akl  = lane >> 4;
    const int arow = lr + ((lane >> 3) & 1) * 8;
    const int bkl  = (lane >> 3) & 1;
    const int brow = lr + (lane >> 4) * 8;
    u32 aoffm[2];
    #pragma unroll
    for (int mt = 0; mt < 2; mt++) aoffm[mt] = (u32)((32 * mw + 16 * mt + arow) * 256);
    u32 boff[4];
    #pragma unroll
    for (int n2 = 0; n2 < 4; n2++) boff[n2] = (u32)((64 * nw + 16 * n2 + brow) * 256);

    #pragma unroll 1
    for (int ks = 0; ks < 8; ks++) {
        const int kc0 = ks * 2;
        const u32 axor = (u32)(((kc0 + akl) ^ lr) << 4);
        const u32 bxor = (u32)(((kc0 + bkl) ^ lr) << 4);
        u32 ah[2][4], b[4][4];
        #pragma unroll
        for (int mt = 0; mt < 2; mt++) ldm_x4(sA + aoffm[mt] + axor, ah[mt]);
        #pragma unroll
        for (int n2 = 0; n2 < 4; n2++) ldm_x4(sB + boff[n2] + bxor, b[n2]);
        #pragma unroll
        for (int mt = 0; mt < 2; mt++)
            #pragma unroll
            for (int nt = 0; nt < 8; nt++)
                mma_f16(acc[mt][nt], ah[mt], &b[nt >> 1][(nt & 1) * 2]);
    }
}

// ---------------- prep: weights -> transposed fp16 swizzled images -------------
__global__ void prep_kernel(const float* __restrict__ W1, const float* __restrict__ W2) {
    int n = threadIdx.x;
    const float* W = (blockIdx.x == 0) ? W1 : (blockIdx.x == 1) ? (W1 + D * D) : W2;
    unsigned char* img = (blockIdx.x == 0) ? g_W1a_h : (blockIdx.x == 1) ? g_W1b_h : g_W2h;
    for (int k = 0; k < D; k++) {
        __half h = __float2half_rn(W[k * D + n]);
        int o = n * 256 + ((((k >> 3) ^ (n & 7))) << 4) + ((k & 7) << 1);
        *(__half*)(img + o) = h;
    }
}

// ---------------- proj: dst = src_rows @ Wimg (+bias), fp16 1-pass, M=128 ------
__global__ void __launch_bounds__(256, 2) proj_kernel(
    const float* __restrict__ V, const int* __restrict__ gidx,
    const float* __restrict__ bias, int n_rows, int n_tiles, int mode)
{
    extern __shared__ char smc[];
    u32 sb = smem_u32(smc);
    const int t = threadIdx.x, w = t >> 5, lane = t & 31;
    const int mw = w >> 1, nw = w & 1;
    const int rr = t >> 2, cc4 = t & 3;

    {   // stage B (fp16, 32KB)
        const float4* src = (const float4*)(mode ? g_W1b_h : g_W1a_h);
        float4* dst = (float4*)(smc + PP_B);
        #pragma unroll
        for (int i = 0; i < 8; i++) dst[t + 256 * i] = src[t + 256 * i];
    }
    float* dstP = mode ? g_Q : g_P;
    const float4* V4 = (const float4*)V;

    for (int tile = blockIdx.x; tile < n_tiles; tile += gridDim.x) {
        __syncthreads();
        #pragma unroll
        for (int h = 0; h < 2; h++) {
            int r = 64 * h + rr;
            int gr = tile * 128 + r; if (gr >= n_rows) gr = n_rows - 1;
            int src = mode ? gidx[gr] : gr;
            const float4* Vr = V4 + (size_t)src * 32;
            #pragma unroll
            for (int m = 0; m < 4; m++) {
                int j = cc4 + 4 * m;
                uint4 hv = pack8h(Vr[2 * j], Vr[2 * j + 1]);
                u32 off = (u32)(r * 256 + ((j ^ (r & 7)) << 4));
                *(uint4*)(smc + PP_A + off) = hv;
            }
        }
        __syncthreads();

        float acc[2][8][4];
        #pragma unroll
        for (int a = 0; a < 2; a++)
            #pragma unroll
            for (int b = 0; b < 8; b++)
                #pragma unroll
                for (int c = 0; c < 4; c++) acc[a][b][c] = 0.f;
        gemm32_1p(sb + PP_A, sb + PP_B, lane, mw, nw, acc);

        #pragma unroll
        for (int mt = 0; mt < 2; mt++)
            #pragma unroll
            for (int nt = 0; nt < 8; nt++) {
                int gr0 = tile * 128 + 32 * mw + 16 * mt + (lane >> 2);
                int gc = 64 * nw + 8 * nt + 2 * (lane & 3);
                float bx = 0.f, by = 0.f;
                if (mode) { bx = bias[gc]; by = bias[gc + 1]; }
                if (gr0 < n_rows)
                    *(float2*)&dstP[(size_t)gr0 * D + gc] =
                        make_float2(acc[mt][nt][0] + bx, acc[mt][nt][1] + by);
                if (gr0 + 8 < n_rows)
                    *(float2*)&dstP[(size_t)(gr0 + 8) * D + gc] =
                        make_float2(acc[mt][nt][2] + bx, acc[mt][nt][3] + by);
            }
    }
}

// ---------------- agg: M=128 (4 nodes), fp16 single-pass HMMA ------------------
__global__ void __launch_bounds__(256, 2) agg_kernel(
    const float* __restrict__ V, const int* __restrict__ neigh,
    const float* __restrict__ b2, const float* __restrict__ W3,
    float* __restrict__ out, int n_nodes, int n_tiles)
{
    extern __shared__ char smc[];
    u32 sb = smem_u32(smc);
    const int t = threadIdx.x, w = t >> 5, lane = t & 31;
    const int mw = w >> 1, nw = w & 1;
    const int rr = t >> 2, cc4 = t & 3;

    float2* b2w3  = (float2*)(smc + AG_BW);
    float4* qst4  = (float4*)(smc + AG_QST);   // [2buf][128]
    int*    idx_s = (int*)(smc + AG_IDX);      // [2buf][128]
    float*  spart = (float*)(smc + AG_SP);     // [2][128]
    float*  att   = (float*)(smc + AG_ATT);    // [128]
    float4* pp4   = (float4*)(smc + AG_A);     // partials overlay (post-GEMM)

    {   // stage B (fp16, 32KB)
        const float4* src = (const float4*)g_W2h;
        float4* dst = (float4*)(smc + AG_B);
        #pragma unroll
        for (int i = 0; i < 8; i++) dst[t + 256 * i] = src[t + 256 * i];
    }
    if (t < D) b2w3[t] = make_float2(b2[t], W3[t]);

    const float4* P4 = (const float4*)g_P;
    const float4* Q4 = (const float4*)g_Q;
    const float4* V4 = (const float4*)V;
    const int idx_max = n_nodes * 32 - 1;

    // prologue: idx + Q for first tile into buffer 0
    {
        int tile0 = blockIdx.x; if (tile0 >= n_tiles) tile0 = n_tiles - 1;
        if (t < 128) {
            int gi = tile0 * 128 + t; if (gi > idx_max) gi = idx_max;
            idx_s[t] = neigh[gi];
            int qr = 4 * tile0 + (t >> 5); if (qr >= n_nodes) qr = n_nodes - 1;
            qst4[t] = Q4[(size_t)qr * 32 + (t & 31)];
        }
    }
    __syncthreads();
    int bp = 0;

    for (int tile = blockIdx.x; tile < n_tiles; tile += gridDim.x) {
        const int cur = bp, nxt = bp ^ 1;

        // convert: A = f16(relu(P[vid] + Q[node])), 128 rows, single pass
        #pragma unroll
        for (int h = 0; h < 2; h++) {
            int r = 64 * h + rr;
            int vid = idx_s[cur * 128 + r];
            const float4* Pr = P4 + (size_t)vid * 32;
            const float4* Qr = qst4 + cur * 128 + (r >> 5) * 32;
            #pragma unroll
            for (int m = 0; m < 4; m++) {
                int j = cc4 + 4 * m;
                float4 p0 = Pr[2 * j], p1 = Pr[2 * j + 1];
                float4 q0 = Qr[2 * j], q1 = Qr[2 * j + 1];
                float4 h0, h1;
                h0.x = fmaxf(p0.x + q0.x, 0.f); h0.y = fmaxf(p0.y + q0.y, 0.f);
                h0.z = fmaxf(p0.z + q0.z, 0.f); h0.w = fmaxf(p0.w + q0.w, 0.f);
                h1.x = fmaxf(p1.x + q1.x, 0.f); h1.y = fmaxf(p1.y + q1.y, 0.f);
                h1.z = fmaxf(p1.z + q1.z, 0.f); h1.w = fmaxf(p1.w + q1.w, 0.f);
                u32 off = (u32)(r * 256 + ((j ^ (r & 7)) << 4));
                *(uint4*)(smc + AG_A + off) = pack8h(h0, h1);
            }
        }
        __syncthreads();   // A ready

        // prefetch next tile's idx + Q (hidden by GEMM)
        int tnext = tile + gridDim.x; if (tnext >= n_tiles) tnext = tile;
        if (t < 128) {
            int gi = tnext * 128 + t; if (gi > idx_max) gi = idx_max;
            idx_s[nxt * 128 + t] = neigh[gi];
            int qr = 4 * tnext + (t >> 5); if (qr >= n_nodes) qr = n_nodes - 1;
            qst4[nxt * 128 + t] = Q4[(size_t)qr * 32 + (t & 31)];
        }

        float acc[2][8][4];
        #pragma unroll
        for (int a = 0; a < 2; a++)
            #pragma unroll
            for (int b = 0; b < 8; b++)
                #pragma unroll
                for (int c = 0; c < 4; c++) acc[a][b][c] = 0.f;
        gemm32_1p(sb + AG_A, sb + AG_B, lane, mw, nw, acc);

        // scores: s[row] = sum_c relu(h2 + b2) * W3
        #pragma unroll
        for (int mt = 0; mt < 2; mt++) {
            float sp0 = 0.f, sp1 = 0.f;
            #pragma unroll
            for (int nt = 0; nt < 8; nt++) {
                int gc = 64 * nw + 8 * nt + 2 * (lane & 3);
                float2 bw0 = b2w3[gc], bw1 = b2w3[gc + 1];
                sp0 += fmaxf(acc[mt][nt][0] + bw0.x, 0.f) * bw0.y + fmaxf(acc[mt][nt][1] + bw1.x, 0.f) * bw1.y;
                sp1 += fmaxf(acc[mt][nt][2] + bw0.x, 0.f) * bw0.y + fmaxf(acc[mt][nt][3] + bw1.x, 0.f) * bw1.y;
            }
            sp0 += __shfl_xor_sync(0xffffffffu, sp0, 1); sp0 += __shfl_xor_sync(0xffffffffu, sp0, 2);
            sp1 += __shfl_xor_sync(0xffffffffu, sp1, 1); sp1 += __shfl_xor_sync(0xffffffffu, sp1, 2);
            if ((lane & 3) == 0) {
                spart[nw * 128 + 32 * mw + 16 * mt + (lane >> 2)]     = sp0;
                spart[nw * 128 + 32 * mw + 16 * mt + 8 + (lane >> 2)] = sp1;
            }
        }
        __syncthreads();   // spart ready; GEMM reads done (A reusable)

        if (w < 4) {       // softmax: warp w = node-local w
            float s = spart[32 * w + lane] + spart[128 + 32 * w + lane];
            float m = s;
            #pragma unroll
            for (int o = 16; o > 0; o >>= 1) m = fmaxf(m, __shfl_xor_sync(0xffffffffu, m, o));
            float ev = expf(s - m);
            float sum = ev;
            #pragma unroll
            for (int o = 16; o > 0; o >>= 1) sum += __shfl_xor_sync(0xffffffffu, sum, o);
            att[32 * w + lane] = ev / sum;
        }
        __syncthreads();

        // aggregate: thread = (node, k-half, col4); partials into A overlay
        {
            int nd = t >> 6, kh = (t >> 5) & 1, c4 = t & 31;
            float4 a4 = make_float4(0.f, 0.f, 0.f, 0.f);
            #pragma unroll
            for (int kk = 0; kk < 16; kk++) {
                int k = 32 * nd + 16 * kh + kk;
                float a = att[k];
                int vid = idx_s[cur * 128 + k];
                float4 v = V4[(size_t)vid * 32 + c4];
                a4.x = fmaf(a, v.x, a4.x); a4.y = fmaf(a, v.y, a4.y);
                a4.z = fmaf(a, v.z, a4.z); a4.w = fmaf(a, v.w, a4.w);
            }
            pp4[(nd * 2 + kh) * 32 + c4] = a4;
        }
        __syncthreads();
        if (t < 128) {
            int nd = t >> 5, c4 = t & 31;
            float4 s0 = pp4[(nd * 2) * 32 + c4];
            float4 s1 = pp4[(nd * 2 + 1) * 32 + c4];
            float4 rv = make_float4(s0.x + s1.x, s0.y + s1.y, s0.z + s1.z, s0.w + s1.w);
            int ng = 4 * tile + nd;
            if (ng < n_nodes) ((float4*)out)[(size_t)ng * 32 + c4] = rv;
        }
        __syncthreads();   // pp4 reads done before next convert overwrites A

        bp ^= 1;
    }
}

// -------------------------------------------------------------------------------
extern "C" void kernel_launch(void* const* d_in, const int* in_sizes, int n_in,
                              void* d_out, int out_size)
{
    const float* V     = (const float*)d_in[0];
    const int*   nodes = (const int*)  d_in[1];
    const int*   neigh = (const int*)  d_in[2];
    const float* W1    = (const float*)d_in[3];
    const float* b1    = (const float*)d_in[4];
    const float* W2    = (const float*)d_in[5];
    const float* b2    = (const float*)d_in[6];
    const float* W3    = (const float*)d_in[7];
    float* out = (float*)d_out;

    const int n_videos = in_sizes[0] / D;
    const int n_nodes  = in_sizes[1];
    const int p_tiles  = (n_videos + 127) / 128;
    const int q_tiles  = (n_nodes + 127) / 128;
    const int a_tiles  = (n_nodes + 3) / 4;

    cudaFuncSetAttribute(proj_kernel, cudaFuncAttributeMaxDynamicSharedMemorySize, PP_SMEM);
    cudaFuncSetAttribute(agg_kernel,  cudaFuncAttributeMaxDynamicSharedMemorySize, AG_SMEM);

    prep_kernel<<<3, 128>>>(W1, W2);
    proj_kernel<<<296, 256, PP_SMEM>>>(V, nullptr, nullptr, n_videos, p_tiles, 0);
    proj_kernel<<<q_tiles, 256, PP_SMEM>>>(V, nodes, b1, n_nodes, q_tiles, 1);
    agg_kernel<<<296, 256, AG_SMEM>>>(V, neigh, b2, W3, out, n_nodes, a_tiles);
}

// round 9
// speedup vs baseline: 5.8982x; 1.0806x over previous
#include <cuda_runtime.h>
#include <cuda_fp16.h>
#include <cstdint>

#define D 128
#define NV_MAX 200000
#define NN_MAX 20000

typedef unsigned long long u64;
typedef unsigned int u32;

// ---------------- device scratch (no allocs allowed) ------------------------
__device__ __align__(16) unsigned char g_Ph[(size_t)NV_MAX * 256]; // P fp16 (51MB)
__device__ __align__(16) unsigned char g_Vh[(size_t)NV_MAX * 256]; // V fp16 (51MB)
__device__ float g_Q[(size_t)NN_MAX * D];              // V[nodes] @ W1b + b1 (fp32)
__device__ __align__(16) unsigned char g_W1a_h[32768]; // W1a^T fp16, swizzled
__device__ __align__(16) unsigned char g_W1b_h[32768]; // W1b^T fp16, swizzled
__device__ __align__(16) unsigned char g_W2h[32768];   // W2^T  fp16, swizzled

// ---------------- smem layouts ------------------------------------------------
#define PP_B    0
#define PP_A    32768
#define PP_SMEM 66560
#define AG_B    0          // B fp16 32K
#define AG_A    32768      // A fp16 32K (overlay: agg partials post-GEMM)
#define AG_BW   65536      // float2 b2/W3 [128]          (1K)
#define AG_QST  66560      // float4 q rows [2buf][128]   (4K)
#define AG_IDX  70656      // int [2buf][128]             (1K)
#define AG_SP   71680      // score partials float[2][128](1K)
#define AG_ATT  72704      // att float[128]              (512B)
#define AG_SMEM 73728

// ---------------- helpers ------------------------------------------------------
__device__ __forceinline__ u32 smem_u32(const void* p) {
    u32 a; asm("{ .reg .u64 t; cvta.to.shared.u64 t, %1; cvt.u32.u64 %0, t; }" : "=r"(a) : "l"(p));
    return a;
}
__device__ __forceinline__ void ldm_x4(u32 addr, u32* r) {
    asm volatile("ldmatrix.sync.aligned.m8n8.x4.shared.b16 {%0,%1,%2,%3}, [%4];"
        : "=r"(r[0]), "=r"(r[1]), "=r"(r[2]), "=r"(r[3]) : "r"(addr));
}
__device__ __forceinline__ void mma_f16(float* c, const u32* a, const u32* b) {
    asm volatile("mma.sync.aligned.m16n8k16.row.col.f32.f16.f16.f32 "
        "{%0,%1,%2,%3}, {%4,%5,%6,%7}, {%8,%9}, {%0,%1,%2,%3};"
        : "+f"(c[0]), "+f"(c[1]), "+f"(c[2]), "+f"(c[3])
        : "r"(a[0]), "r"(a[1]), "r"(a[2]), "r"(a[3]), "r"(b[0]), "r"(b[1]));
}
__device__ __forceinline__ uint4 pack8h(float4 a, float4 b) {
    __half2 h0 = __floats2half2_rn(a.x, a.y);
    __half2 h1 = __floats2half2_rn(a.z, a.w);
    __half2 h2 = __floats2half2_rn(b.x, b.y);
    __half2 h3 = __floats2half2_rn(b.z, b.w);
    return make_uint4(*(u32*)&h0, *(u32*)&h1, *(u32*)&h2, *(u32*)&h3);
}

// ---------------- GEMM: block 128x128, warp 32x64, fp16 single-pass ------------
__device__ __forceinline__ void gemm32_1p(u32 sA, u32 sB, int lane, int mw, int nw,
                                          float (&acc)[2][8][4]) {
    const int lr   = lane & 7;
    const int akl  = lane >> 4;
    const int arow = lr + ((lane >> 3) & 1) * 8;
    const int bkl  = (lane >> 3) & 1;
    const int brow = lr + (lane >> 4) * 8;
    u32 aoffm[2];
    #pragma unroll
    for (int mt = 0; mt < 2; mt++) aoffm[mt] = (u32)((32 * mw + 16 * mt + arow) * 256);
    u32 boff[4];
    #pragma unroll
    for (int n2 = 0; n2 < 4; n2++) boff[n2] = (u32)((64 * nw + 16 * n2 + brow) * 256);

    #pragma unroll 1
    for (int ks = 0; ks < 8; ks++) {
        const int kc0 = ks * 2;
        const u32 axor = (u32)(((kc0 + akl) ^ lr) << 4);
        const u32 bxor = (u32)(((kc0 + bkl) ^ lr) << 4);
        u32 ah[2][4], b[4][4];
        #pragma unroll
        for (int mt = 0; mt < 2; mt++) ldm_x4(sA + aoffm[mt] + axor, ah[mt]);
        #pragma unroll
        for (int n2 = 0; n2 < 4; n2++) ldm_x4(sB + boff[n2] + bxor, b[n2]);
        #pragma unroll
        for (int mt = 0; mt < 2; mt++)
            #pragma unroll
            for (int nt = 0; nt < 8; nt++)
                mma_f16(acc[mt][nt], ah[mt], &b[nt >> 1][(nt & 1) * 2]);
    }
}

// ---------------- prep: weights -> transposed fp16 swizzled images -------------
__global__ void prep_kernel(const float* __restrict__ W1, const float* __restrict__ W2) {
    int n = threadIdx.x;
    const float* W = (blockIdx.x == 0) ? W1 : (blockIdx.x == 1) ? (W1 + D * D) : W2;
    unsigned char* img = (blockIdx.x == 0) ? g_W1a_h : (blockIdx.x == 1) ? g_W1b_h : g_W2h;
    for (int k = 0; k < D; k++) {
        __half h = __float2half_rn(W[k * D + n]);
        int o = n * 256 + ((((k >> 3) ^ (n & 7))) << 4) + ((k & 7) << 1);
        *(__half*)(img + o) = h;
    }
}

// ---------------- proj: fp16 1-pass, M=128 -------------------------------------
// mode 0: P = V @ W1a -> g_Ph (fp16); also emits g_Vh = f16(V)
// mode 1: Q = V[nodes] @ W1b + b1 -> g_Q (fp32)
__global__ void __launch_bounds__(256, 2) proj_kernel(
    const float* __restrict__ V, const int* __restrict__ gidx,
    const float* __restrict__ bias, int n_rows, int n_tiles, int mode)
{
    extern __shared__ char smc[];
    u32 sb = smem_u32(smc);
    const int t = threadIdx.x, w = t >> 5, lane = t & 31;
    const int mw = w >> 1, nw = w & 1;
    const int rr = t >> 2, cc4 = t & 3;

    {   // stage B (fp16, 32KB)
        const float4* src = (const float4*)(mode ? g_W1b_h : g_W1a_h);
        float4* dst = (float4*)(smc + PP_B);
        #pragma unroll
        for (int i = 0; i < 8; i++) dst[t + 256 * i] = src[t + 256 * i];
    }
    const float4* V4 = (const float4*)V;
    uint4* Vh4 = (uint4*)g_Vh;

    for (int tile = blockIdx.x; tile < n_tiles; tile += gridDim.x) {
        __syncthreads();
        #pragma unroll
        for (int h = 0; h < 2; h++) {
            int r = 64 * h + rr;
            int gr = tile * 128 + r; if (gr >= n_rows) gr = n_rows - 1;
            int src = mode ? gidx[gr] : gr;
            const float4* Vr = V4 + (size_t)src * 32;
            #pragma unroll
            for (int m = 0; m < 4; m++) {
                int j = cc4 + 4 * m;
                uint4 hv = pack8h(Vr[2 * j], Vr[2 * j + 1]);
                u32 off = (u32)(r * 256 + ((j ^ (r & 7)) << 4));
                *(uint4*)(smc + PP_A + off) = hv;
                if (!mode) Vh4[(size_t)gr * 16 + j] = hv;   // free fp16 V copy
            }
        }
        __syncthreads();

        float acc[2][8][4];
        #pragma unroll
        for (int a = 0; a < 2; a++)
            #pragma unroll
            for (int b = 0; b < 8; b++)
                #pragma unroll
                for (int c = 0; c < 4; c++) acc[a][b][c] = 0.f;
        gemm32_1p(sb + PP_A, sb + PP_B, lane, mw, nw, acc);

        #pragma unroll
        for (int mt = 0; mt < 2; mt++)
            #pragma unroll
            for (int nt = 0; nt < 8; nt++) {
                int gr0 = tile * 128 + 32 * mw + 16 * mt + (lane >> 2);
                int gc = 64 * nw + 8 * nt + 2 * (lane & 3);
                if (mode) {
                    float bx = bias[gc], by = bias[gc + 1];
                    if (gr0 < n_rows)
                        *(float2*)&g_Q[(size_t)gr0 * D + gc] =
                            make_float2(acc[mt][nt][0] + bx, acc[mt][nt][1] + by);
                    if (gr0 + 8 < n_rows)
                        *(float2*)&g_Q[(size_t)(gr0 + 8) * D + gc] =
                            make_float2(acc[mt][nt][2] + bx, acc[mt][nt][3] + by);
                } else {
                    __half2 ha = __floats2half2_rn(acc[mt][nt][0], acc[mt][nt][1]);
                    __half2 hb = __floats2half2_rn(acc[mt][nt][2], acc[mt][nt][3]);
                    if (gr0 < n_rows)
                        ((u32*)g_Ph)[(size_t)gr0 * 64 + (gc >> 1)] = *(u32*)&ha;
                    if (gr0 + 8 < n_rows)
                        ((u32*)g_Ph)[(size_t)(gr0 + 8) * 64 + (gc >> 1)] = *(u32*)&hb;
                }
            }
    }
}

// ---------------- agg: M=128 (4 nodes), fp16 gathers everywhere ----------------
__global__ void __launch_bounds__(256, 2) agg_kernel(
    const int* __restrict__ neigh,
    const float* __restrict__ b2, const float* __restrict__ W3,
    float* __restrict__ out, int n_nodes, int n_tiles)
{
    extern __shared__ char smc[];
    u32 sb = smem_u32(smc);
    const int t = threadIdx.x, w = t >> 5, lane = t & 31;
    const int mw = w >> 1, nw = w & 1;
    const int rr = t >> 2, cc4 = t & 3;

    float2* b2w3  = (float2*)(smc + AG_BW);
    float4* qst4  = (float4*)(smc + AG_QST);   // [2buf][128]
    int*    idx_s = (int*)(smc + AG_IDX);      // [2buf][128]
    float*  spart = (float*)(smc + AG_SP);     // [2][128]
    float*  att   = (float*)(smc + AG_ATT);    // [128]
    float4* pp4   = (float4*)(smc + AG_A);     // partials overlay (post-GEMM)

    {   // stage B (fp16, 32KB)
        const float4* src = (const float4*)g_W2h;
        float4* dst = (float4*)(smc + AG_B);
        #pragma unroll
        for (int i = 0; i < 8; i++) dst[t + 256 * i] = src[t + 256 * i];
    }
    if (t < D) b2w3[t] = make_float2(b2[t], W3[t]);

    const uint4*  Ph4 = (const uint4*)g_Ph;
    const uint4*  Vh4 = (const uint4*)g_Vh;
    const float4* Q4  = (const float4*)g_Q;
    const int idx_max = n_nodes * 32 - 1;

    {   // prologue: idx + Q for first tile into buffer 0
        int tile0 = blockIdx.x; if (tile0 >= n_tiles) tile0 = n_tiles - 1;
        if (t < 128) {
            int gi = tile0 * 128 + t; if (gi > idx_max) gi = idx_max;
            idx_s[t] = neigh[gi];
            int qr = 4 * tile0 + (t >> 5); if (qr >= n_nodes) qr = n_nodes - 1;
            qst4[t] = Q4[(size_t)qr * 32 + (t & 31)];
        }
    }
    __syncthreads();
    int bp = 0;

    for (int tile = blockIdx.x; tile < n_tiles; tile += gridDim.x) {
        const int cur = bp, nxt = bp ^ 1;

        // convert: A = f16(relu(f16P[vid] + Q[node])), 128 rows
        #pragma unroll
        for (int h = 0; h < 2; h++) {
            int r = 64 * h + rr;
            int vid = idx_s[cur * 128 + r];
            const uint4* Pr = Ph4 + (size_t)vid * 16;
            const float4* Qr = qst4 + cur * 128 + (r >> 5) * 32;
            #pragma unroll
            for (int m = 0; m < 4; m++) {
                int j = cc4 + 4 * m;
                uint4 ph = Pr[j];
                float4 q0 = Qr[2 * j], q1 = Qr[2 * j + 1];
                float2 f0 = __half22float2(*(__half2*)&ph.x);
                float2 f1 = __half22float2(*(__half2*)&ph.y);
                float2 f2 = __half22float2(*(__half2*)&ph.z);
                float2 f3 = __half22float2(*(__half2*)&ph.w);
                float4 h0, h1;
                h0.x = fmaxf(f0.x + q0.x, 0.f); h0.y = fmaxf(f0.y + q0.y, 0.f);
                h0.z = fmaxf(f1.x + q0.z, 0.f); h0.w = fmaxf(f1.y + q0.w, 0.f);
                h1.x = fmaxf(f2.x + q1.x, 0.f); h1.y = fmaxf(f2.y + q1.y, 0.f);
                h1.z = fmaxf(f3.x + q1.z, 0.f); h1.w = fmaxf(f3.y + q1.w, 0.f);
                u32 off = (u32)(r * 256 + ((j ^ (r & 7)) << 4));
                *(uint4*)(smc + AG_A + off) = pack8h(h0, h1);
            }
        }
        __syncthreads();   // A ready

        // prefetch next tile's idx + Q (hidden by GEMM)
        int tnext = tile + gridDim.x; if (tnext >= n_tiles) tnext = tile;
        if (t < 128) {
            int gi = tnext * 128 + t; if (gi > idx_max) gi = idx_max;
            idx_s[nxt * 128 + t] = neigh[gi];
            int qr = 4 * tnext + (t >> 5); if (qr >= n_nodes) qr = n_nodes - 1;
            qst4[nxt * 128 + t] = Q4[(size_t)qr * 32 + (t & 31)];
        }

        float acc[2][8][4];
        #pragma unroll
        for (int a = 0; a < 2; a++)
            #pragma unroll
            for (int b = 0; b < 8; b++)
                #pragma unroll
                for (int c = 0; c < 4; c++) acc[a][b][c] = 0.f;
        gemm32_1p(sb + AG_A, sb + AG_B, lane, mw, nw, acc);

        // scores: s[row] = sum_c relu(h2 + b2) * W3
        #pragma unroll
        for (int mt = 0; mt < 2; mt++) {
            float sp0 = 0.f, sp1 = 0.f;
            #pragma unroll
            for (int nt = 0; nt < 8; nt++) {
                int gc = 64 * nw + 8 * nt + 2 * (lane & 3);
                float2 bw0 = b2w3[gc], bw1 = b2w3[gc + 1];
                sp0 += fmaxf(acc[mt][nt][0] + bw0.x, 0.f) * bw0.y + fmaxf(acc[mt][nt][1] + bw1.x, 0.f) * bw1.y;
                sp1 += fmaxf(acc[mt][nt][2] + bw0.x, 0.f) * bw0.y + fmaxf(acc[mt][nt][3] + bw1.x, 0.f) * bw1.y;
            }
            sp0 += __shfl_xor_sync(0xffffffffu, sp0, 1); sp0 += __shfl_xor_sync(0xffffffffu, sp0, 2);
            sp1 += __shfl_xor_sync(0xffffffffu, sp1, 1); sp1 += __shfl_xor_sync(0xffffffffu, sp1, 2);
            if ((lane & 3) == 0) {
                spart[nw * 128 + 32 * mw + 16 * mt + (lane >> 2)]     = sp0;
                spart[nw * 128 + 32 * mw + 16 * mt + 8 + (lane >> 2)] = sp1;
            }
        }
        __syncthreads();   // spart ready; GEMM reads done (A reusable)

        if (w < 4) {       // softmax: warp w = node-local w
            float s = spart[32 * w + lane] + spart[128 + 32 * w + lane];
            float m = s;
            #pragma unroll
            for (int o = 16; o > 0; o >>= 1) m = fmaxf(m, __shfl_xor_sync(0xffffffffu, m, o));
            float ev = expf(s - m);
            float sum = ev;
            #pragma unroll
            for (int o = 16; o > 0; o >>= 1) sum += __shfl_xor_sync(0xffffffffu, sum, o);
            att[32 * w + lane] = ev / sum;
        }
        __syncthreads();

        // aggregate from fp16 V: thread = (node, k-quarter, 8-col chunk)
        {
            int nd = t >> 6, kq = (t >> 4) & 3, c8 = t & 15;
            float a8[8];
            #pragma unroll
            for (int i = 0; i < 8; i++) a8[i] = 0.f;
            #pragma unroll
            for (int kk = 0; kk < 8; kk++) {
                int k = 32 * nd + 8 * kq + kk;
                float a = att[k];
                int vid = idx_s[cur * 128 + k];
                uint4 v = Vh4[(size_t)vid * 16 + c8];
                float2 f0 = __half22float2(*(__half2*)&v.x);
                float2 f1 = __half22float2(*(__half2*)&v.y);
                float2 f2 = __half22float2(*(__half2*)&v.z);
                float2 f3 = __half22float2(*(__half2*)&v.w);
                a8[0] = fmaf(a, f0.x, a8[0]); a8[1] = fmaf(a, f0.y, a8[1]);
                a8[2] = fmaf(a, f1.x, a8[2]); a8[3] = fmaf(a, f1.y, a8[3]);
                a8[4] = fmaf(a, f2.x, a8[4]); a8[5] = fmaf(a, f2.y, a8[5]);
                a8[6] = fmaf(a, f3.x, a8[6]); a8[7] = fmaf(a, f3.y, a8[7]);
            }
            pp4[(nd * 4 + kq) * 32 + c8 * 2]     = make_float4(a8[0], a8[1], a8[2], a8[3]);
            pp4[(nd * 4 + kq) * 32 + c8 * 2 + 1] = make_float4(a8[4], a8[5], a8[6], a8[7]);
        }
        __syncthreads();
        if (t < 128) {
            int nd = t >> 5, c4 = t & 31;
            float4 s0 = pp4[(nd * 4 + 0) * 32 + c4];
            float4 s1 = pp4[(nd * 4 + 1) * 32 + c4];
            float4 s2 = pp4[(nd * 4 + 2) * 32 + c4];
            float4 s3 = pp4[(nd * 4 + 3) * 32 + c4];
            float4 rv = make_float4(s0.x + s1.x + s2.x + s3.x, s0.y + s1.y + s2.y + s3.y,
                                    s0.z + s1.z + s2.z + s3.z, s0.w + s1.w + s2.w + s3.w);
            int ng = 4 * tile + nd;
            if (ng < n_nodes) ((float4*)out)[(size_t)ng * 32 + c4] = rv;
        }
        __syncthreads();   // pp4 reads done before next convert overwrites A

        bp ^= 1;
    }
}

// -------------------------------------------------------------------------------
extern "C" void kernel_launch(void* const* d_in, const int* in_sizes, int n_in,
                              void* d_out, int out_size)
{
    const float* V     = (const float*)d_in[0];
    const int*   nodes = (const int*)  d_in[1];
    const int*   neigh = (const int*)  d_in[2];
    const float* W1    = (const float*)d_in[3];
    const float* b1    = (const float*)d_in[4];
    const float* W2    = (const float*)d_in[5];
    const float* b2    = (const float*)d_in[6];
    const float* W3    = (const float*)d_in[7];
    float* out = (float*)d_out;

    const int n_videos = in_sizes[0] / D;
    const int n_nodes  = in_sizes[1];
    const int p_tiles  = (n_videos + 127) / 128;
    const int q_tiles  = (n_nodes + 127) / 128;
    const int a_tiles  = (n_nodes + 3) / 4;

    cudaFuncSetAttribute(proj_kernel, cudaFuncAttributeMaxDynamicSharedMemorySize, PP_SMEM);
    cudaFuncSetAttribute(agg_kernel,  cudaFuncAttributeMaxDynamicSharedMemorySize, AG_SMEM);

    prep_kernel<<<3, 128>>>(W1, W2);
    proj_kernel<<<296, 256, PP_SMEM>>>(V, nullptr, nullptr, n_videos, p_tiles, 0);
    proj_kernel<<<q_tiles, 256, PP_SMEM>>>(V, nodes, b1, n_nodes, q_tiles, 1);
    agg_kernel<<<296, 256, AG_SMEM>>>(neigh, b2, W3, out, n_nodes, a_tiles);
}

// round 10
// speedup vs baseline: 5.9285x; 1.0051x over previous
#include <cuda_runtime.h>
#include <cuda_fp16.h>
#include <cstdint>

#define D 128
#define NV_MAX 200000
#define NN_MAX 20000

typedef unsigned long long u64;
typedef unsigned int u32;

// ---------------- device scratch (no allocs allowed) ------------------------
__device__ __align__(16) unsigned char g_Ph[(size_t)NV_MAX * 256]; // P fp16 (51MB)
__device__ __align__(16) unsigned char g_Vh[(size_t)NV_MAX * 256]; // V fp16 (51MB)
__device__ __align__(16) unsigned char g_Qh[(size_t)NN_MAX * 256]; // Q fp16 (5MB)

// ---------------- smem layouts ------------------------------------------------
// proj (96KB + pad -> 2 CTAs/SM)
#define PP_B0   0
#define PP_B1   32768
#define PP_A    65536
#define PP_BS   98304      // float b1 [128]
#define PP_SMEM 99328
// agg (~70KB -> 2 CTAs/SM)
#define AG_B    0          // B fp16 32K
#define AG_A    32768      // A fp16 32K (overlay: agg partials post-GEMM)
#define AG_BW   65536      // float2 b2/W3 [128]          (1K)
#define AG_QST  66560      // uint4 q rows [2buf][64]     (2K)
#define AG_IDX  68608      // int [2buf][128]             (1K)
#define AG_SP   69632      // score partials float[2][128](1K)
#define AG_ATT  70656      // att float[128]              (512B)
#define AG_SMEM 71680

// ---------------- helpers ------------------------------------------------------
__device__ __forceinline__ u32 smem_u32(const void* p) {
    u32 a; asm("{ .reg .u64 t; cvta.to.shared.u64 t, %1; cvt.u32.u64 %0, t; }" : "=r"(a) : "l"(p));
    return a;
}
__device__ __forceinline__ void ldm_x4(u32 addr, u32* r) {
    asm volatile("ldmatrix.sync.aligned.m8n8.x4.shared.b16 {%0,%1,%2,%3}, [%4];"
        : "=r"(r[0]), "=r"(r[1]), "=r"(r[2]), "=r"(r[3]) : "r"(addr));
}
__device__ __forceinline__ void mma_f16(float* c, const u32* a, const u32* b) {
    asm volatile("mma.sync.aligned.m16n8k16.row.col.f32.f16.f16.f32 "
        "{%0,%1,%2,%3}, {%4,%5,%6,%7}, {%8,%9}, {%0,%1,%2,%3};"
        : "+f"(c[0]), "+f"(c[1]), "+f"(c[2]), "+f"(c[3])
        : "r"(a[0]), "r"(a[1]), "r"(a[2]), "r"(a[3]), "r"(b[0]), "r"(b[1]));
}
__device__ __forceinline__ uint4 pack8h(float4 a, float4 b) {
    __half2 h0 = __floats2half2_rn(a.x, a.y);
    __half2 h1 = __floats2half2_rn(a.z, a.w);
    __half2 h2 = __floats2half2_rn(b.x, b.y);
    __half2 h3 = __floats2half2_rn(b.z, b.w);
    return make_uint4(*(u32*)&h0, *(u32*)&h1, *(u32*)&h2, *(u32*)&h3);
}
// relu(a + b) in packed half2 (u32-typed)
__device__ __forceinline__ u32 haddrelu2(u32 a, u32 b) {
    __half2 s = __hadd2(*(__half2*)&a, *(__half2*)&b);
    __half2 z = *(__half2*)&(u32&)(const u32&)a;  // placeholder, replaced below
    (void)z;
    u32 zero = 0u;
    __half2 r = __hmax2(s, *(__half2*)&zero);
    return *(u32*)&r;
}

// stage a fp16 transposed+swizzled weight image from fp32 W[k*D+n]
__device__ __forceinline__ void build_wimg(char* dst, const float* __restrict__ W, int t) {
    int n = t & 127, kh = t >> 7;               // thread covers 64 k values
    #pragma unroll 8
    for (int kk = 0; kk < 64; kk++) {
        int k = kh * 64 + kk;
        __half h = __float2half_rn(W[k * D + n]);
        int o = n * 256 + ((((k >> 3) ^ (n & 7))) << 4) + ((k & 7) << 1);
        *(__half*)(dst + o) = h;
    }
}

// ---------------- GEMM: block 128x128, warp 32x64, fp16 single-pass ------------
__device__ __forceinline__ void gemm32_1p(u32 sA, u32 sB, int lane, int mw, int nw,
                                          float (&acc)[2][8][4]) {
    const int lr   = lane & 7;
    const int akl  = lane >> 4;
    const int arow = lr + ((lane >> 3) & 1) * 8;
    const int bkl  = (lane >> 3) & 1;
    const int brow = lr + (lane >> 4) * 8;
    u32 aoffm[2];
    #pragma unroll
    for (int mt = 0; mt < 2; mt++) aoffm[mt] = (u32)((32 * mw + 16 * mt + arow) * 256);
    u32 boff[4];
    #pragma unroll
    for (int n2 = 0; n2 < 4; n2++) boff[n2] = (u32)((64 * nw + 16 * n2 + brow) * 256);

    #pragma unroll 1
    for (int ks = 0; ks < 8; ks++) {
        const int kc0 = ks * 2;
        const u32 axor = (u32)(((kc0 + akl) ^ lr) << 4);
        const u32 bxor = (u32)(((kc0 + bkl) ^ lr) << 4);
        u32 ah[2][4], b[4][4];
        #pragma unroll
        for (int mt = 0; mt < 2; mt++) ldm_x4(sA + aoffm[mt] + axor, ah[mt]);
        #pragma unroll
        for (int n2 = 0; n2 < 4; n2++) ldm_x4(sB + boff[n2] + bxor, b[n2]);
        #pragma unroll
        for (int mt = 0; mt < 2; mt++)
            #pragma unroll
            for (int nt = 0; nt < 8; nt++)
                mma_f16(acc[mt][nt], ah[mt], &b[nt >> 1][(nt & 1) * 2]);
    }
}

// ---------------- proj: P, Vh, Q in one persistent kernel ----------------------
// tiles [0, p_tiles): P = V @ W1a -> g_Ph, Vh = f16(V)
// tiles [p_tiles, p_tiles+q_tiles): Q = f16(V[nodes] @ W1b + b1) -> g_Qh
__global__ void __launch_bounds__(256, 2) proj_kernel(
    const float* __restrict__ V, const int* __restrict__ gidx,
    const float* __restrict__ W1, const float* __restrict__ b1,
    int n_videos, int n_nodes, int p_tiles, int q_tiles)
{
    extern __shared__ char smc[];
    u32 sb = smem_u32(smc);
    const int t = threadIdx.x, w = t >> 5, lane = t & 31;
    const int mw = w >> 1, nw = w & 1;
    const int rr = t >> 2, cc4 = t & 3;

    build_wimg(smc + PP_B0, W1, t);          // W1a
    build_wimg(smc + PP_B1, W1 + D * D, t);  // W1b
    if (t < D) ((float*)(smc + PP_BS))[t] = b1[t];

    const float4* V4 = (const float4*)V;
    uint4* Vh4 = (uint4*)g_Vh;
    const int n_total = p_tiles + q_tiles;

    for (int it = blockIdx.x; it < n_total; it += gridDim.x) {
        const int mode = (it >= p_tiles);
        const int tile = mode ? (it - p_tiles) : it;
        const int n_rows = mode ? n_nodes : n_videos;
        __syncthreads();
        #pragma unroll
        for (int h = 0; h < 2; h++) {
            int r = 64 * h + rr;
            int gr = tile * 128 + r; if (gr >= n_rows) gr = n_rows - 1;
            int src = mode ? gidx[gr] : gr;
            const float4* Vr = V4 + (size_t)src * 32;
            #pragma unroll
            for (int m = 0; m < 4; m++) {
                int j = cc4 + 4 * m;
                uint4 hv = pack8h(Vr[2 * j], Vr[2 * j + 1]);
                u32 off = (u32)(r * 256 + ((j ^ (r & 7)) << 4));
                *(uint4*)(smc + PP_A + off) = hv;
                if (!mode) Vh4[(size_t)gr * 16 + j] = hv;   // free fp16 V copy
            }
        }
        __syncthreads();

        float acc[2][8][4];
        #pragma unroll
        for (int a = 0; a < 2; a++)
            #pragma unroll
            for (int b = 0; b < 8; b++)
                #pragma unroll
                for (int c = 0; c < 4; c++) acc[a][b][c] = 0.f;
        gemm32_1p(sb + PP_A, sb + (mode ? PP_B1 : PP_B0), lane, mw, nw, acc);

        const float* b1s = (const float*)(smc + PP_BS);
        #pragma unroll
        for (int mt = 0; mt < 2; mt++)
            #pragma unroll
            for (int nt = 0; nt < 8; nt++) {
                int gr0 = tile * 128 + 32 * mw + 16 * mt + (lane >> 2);
                int gc = 64 * nw + 8 * nt + 2 * (lane & 3);
                float bx = mode ? b1s[gc] : 0.f;
                float by = mode ? b1s[gc + 1] : 0.f;
                __half2 ha = __floats2half2_rn(acc[mt][nt][0] + bx, acc[mt][nt][1] + by);
                __half2 hb = __floats2half2_rn(acc[mt][nt][2] + bx, acc[mt][nt][3] + by);
                u32* dst = mode ? (u32*)g_Qh : (u32*)g_Ph;
                if (gr0 < n_rows)     dst[(size_t)gr0 * 64 + (gc >> 1)] = *(u32*)&ha;
                if (gr0 + 8 < n_rows) dst[(size_t)(gr0 + 8) * 64 + (gc >> 1)] = *(u32*)&hb;
            }
    }
}

// ---------------- agg: M=128 (4 nodes), all-fp16 data path ---------------------
__global__ void __launch_bounds__(256, 2) agg_kernel(
    const int* __restrict__ neigh, const float* __restrict__ W2,
    const float* __restrict__ b2, const float* __restrict__ W3,
    float* __restrict__ out, int n_nodes, int n_tiles)
{
    extern __shared__ char smc[];
    u32 sb = smem_u32(smc);
    const int t = threadIdx.x, w = t >> 5, lane = t & 31;
    const int mw = w >> 1, nw = w & 1;
    const int rr = t >> 2, cc4 = t & 3;

    float2* b2w3  = (float2*)(smc + AG_BW);
    uint4*  qst   = (uint4*)(smc + AG_QST);    // [2buf][64]
    int*    idx_s = (int*)(smc + AG_IDX);      // [2buf][128]
    float*  spart = (float*)(smc + AG_SP);     // [2][128]
    float*  att   = (float*)(smc + AG_ATT);    // [128]
    float4* pp4   = (float4*)(smc + AG_A);     // partials overlay (post-GEMM)

    build_wimg(smc + AG_B, W2, t);
    if (t < D) b2w3[t] = make_float2(b2[t], W3[t]);

    const uint4* Ph4 = (const uint4*)g_Ph;
    const uint4* Vh4 = (const uint4*)g_Vh;
    const uint4* Qh4 = (const uint4*)g_Qh;
    const int idx_max = n_nodes * 32 - 1;

    {   // prologue: idx + Q for first tile into buffer 0
        int tile0 = blockIdx.x; if (tile0 >= n_tiles) tile0 = n_tiles - 1;
        if (t < 128) {
            int gi = tile0 * 128 + t; if (gi > idx_max) gi = idx_max;
            idx_s[t] = neigh[gi];
        }
        if (t < 64) {
            int qr = 4 * tile0 + (t >> 4); if (qr >= n_nodes) qr = n_nodes - 1;
            qst[t] = Qh4[(size_t)qr * 16 + (t & 15)];
        }
    }
    __syncthreads();
    int bp = 0;

    for (int tile = blockIdx.x; tile < n_tiles; tile += gridDim.x) {
        const int cur = bp, nxt = bp ^ 1;

        // convert: A = hmax2(hadd2(Ph[vid], Qh[node]), 0) -- pure half2 path
        #pragma unroll
        for (int h = 0; h < 2; h++) {
            int r = 64 * h + rr;
            int vid = idx_s[cur * 128 + r];
            const uint4* Pr = Ph4 + (size_t)vid * 16;
            const uint4* Qr = qst + cur * 64 + (r >> 5) * 16;
            #pragma unroll
            for (int m = 0; m < 4; m++) {
                int j = cc4 + 4 * m;
                uint4 p = Pr[j], q = Qr[j];
                uint4 o;
                o.x = haddrelu2(p.x, q.x); o.y = haddrelu2(p.y, q.y);
                o.z = haddrelu2(p.z, q.z); o.w = haddrelu2(p.w, q.w);
                u32 off = (u32)(r * 256 + ((j ^ (r & 7)) << 4));
                *(uint4*)(smc + AG_A + off) = o;
            }
        }
        __syncthreads();   // A ready

        // prefetch next tile's idx + Q (hidden by GEMM)
        int tnext = tile + gridDim.x; if (tnext >= n_tiles) tnext = tile;
        if (t < 128) {
            int gi = tnext * 128 + t; if (gi > idx_max) gi = idx_max;
            idx_s[nxt * 128 + t] = neigh[gi];
        }
        if (t < 64) {
            int qr = 4 * tnext + (t >> 4); if (qr >= n_nodes) qr = n_nodes - 1;
            qst[nxt * 64 + t] = Qh4[(size_t)qr * 16 + (t & 15)];
        }

        float acc[2][8][4];
        #pragma unroll
        for (int a = 0; a < 2; a++)
            #pragma unroll
            for (int b = 0; b < 8; b++)
                #pragma unroll
                for (int c = 0; c < 4; c++) acc[a][b][c] = 0.f;
        gemm32_1p(sb + AG_A, sb + AG_B, lane, mw, nw, acc);

        // scores: s[row] = sum_c relu(h2 + b2) * W3
        #pragma unroll
        for (int mt = 0; mt < 2; mt++) {
            float sp0 = 0.f, sp1 = 0.f;
            #pragma unroll
            for (int nt = 0; nt < 8; nt++) {
                int gc = 64 * nw + 8 * nt + 2 * (lane & 3);
                float2 bw0 = b2w3[gc], bw1 = b2w3[gc + 1];
                sp0 += fmaxf(acc[mt][nt][0] + bw0.x, 0.f) * bw0.y + fmaxf(acc[mt][nt][1] + bw1.x, 0.f) * bw1.y;
                sp1 += fmaxf(acc[mt][nt][2] + bw0.x, 0.f) * bw0.y + fmaxf(acc[mt][nt][3] + bw1.x, 0.f) * bw1.y;
            }
            sp0 += __shfl_xor_sync(0xffffffffu, sp0, 1); sp0 += __shfl_xor_sync(0xffffffffu, sp0, 2);
            sp1 += __shfl_xor_sync(0xffffffffu, sp1, 1); sp1 += __shfl_xor_sync(0xffffffffu, sp1, 2);
            if ((lane & 3) == 0) {
                spart[nw * 128 + 32 * mw + 16 * mt + (lane >> 2)]     = sp0;
                spart[nw * 128 + 32 * mw + 16 * mt + 8 + (lane >> 2)] = sp1;
            }
        }
        __syncthreads();   // spart ready; GEMM reads done (A reusable)

        if (w < 4) {       // softmax: warp w = node-local w
            float s = spart[32 * w + lane] + spart[128 + 32 * w + lane];
            float m = s;
            #pragma unroll
            for (int o = 16; o > 0; o >>= 1) m = fmaxf(m, __shfl_xor_sync(0xffffffffu, m, o));
            float ev = expf(s - m);
            float sum = ev;
            #pragma unroll
            for (int o = 16; o > 0; o >>= 1) sum += __shfl_xor_sync(0xffffffffu, sum, o);
            att[32 * w + lane] = ev / sum;
        }
        __syncthreads();

        // aggregate from fp16 V: thread = (node, k-quarter, 8-col chunk)
        {
            int nd = t >> 6, kq = (t >> 4) & 3, c8 = t & 15;
            float a8[8];
            #pragma unroll
            for (int i = 0; i < 8; i++) a8[i] = 0.f;
            #pragma unroll
            for (int kk = 0; kk < 8; kk++) {
                int k = 32 * nd + 8 * kq + kk;
                float a = att[k];
                int vid = idx_s[cur * 128 + k];
                uint4 v = Vh4[(size_t)vid * 16 + c8];
                float2 f0 = __half22float2(*(__half2*)&v.x);
                float2 f1 = __half22float2(*(__half2*)&v.y);
                float2 f2 = __half22float2(*(__half2*)&v.z);
                float2 f3 = __half22float2(*(__half2*)&v.w);
                a8[0] = fmaf(a, f0.x, a8[0]); a8[1] = fmaf(a, f0.y, a8[1]);
                a8[2] = fmaf(a, f1.x, a8[2]); a8[3] = fmaf(a, f1.y, a8[3]);
                a8[4] = fmaf(a, f2.x, a8[4]); a8[5] = fmaf(a, f2.y, a8[5]);
                a8[6] = fmaf(a, f3.x, a8[6]); a8[7] = fmaf(a, f3.y, a8[7]);
            }
            pp4[(nd * 4 + kq) * 32 + c8 * 2]     = make_float4(a8[0], a8[1], a8[2], a8[3]);
            pp4[(nd * 4 + kq) * 32 + c8 * 2 + 1] = make_float4(a8[4], a8[5], a8[6], a8[7]);
        }
        __syncthreads();
        if (t < 128) {
            int nd = t >> 5, c4 = t & 31;
            float4 s0 = pp4[(nd * 4 + 0) * 32 + c4];
            float4 s1 = pp4[(nd * 4 + 1) * 32 + c4];
            float4 s2 = pp4[(nd * 4 + 2) * 32 + c4];
            float4 s3 = pp4[(nd * 4 + 3) * 32 + c4];
            float4 rv = make_float4(s0.x + s1.x + s2.x + s3.x, s0.y + s1.y + s2.y + s3.y,
                                    s0.z + s1.z + s2.z + s3.z, s0.w + s1.w + s2.w + s3.w);
            int ng = 4 * tile + nd;
            if (ng < n_nodes) ((float4*)out)[(size_t)ng * 32 + c4] = rv;
        }
        __syncthreads();   // pp4 reads done before next convert overwrites A

        bp ^= 1;
    }
}

// -------------------------------------------------------------------------------
extern "C" void kernel_launch(void* const* d_in, const int* in_sizes, int n_in,
                              void* d_out, int out_size)
{
    const float* V     = (const float*)d_in[0];
    const int*   nodes = (const int*)  d_in[1];
    const int*   neigh = (const int*)  d_in[2];
    const float* W1    = (const float*)d_in[3];
    const float* b1    = (const float*)d_in[4];
    const float* W2    = (const float*)d_in[5];
    const float* b2    = (const float*)d_in[6];
    const float* W3    = (const float*)d_in[7];
    float* out = (float*)d_out;

    const int n_videos = in_sizes[0] / D;
    const int n_nodes  = in_sizes[1];
    const int p_tiles  = (n_videos + 127) / 128;
    const int q_tiles  = (n_nodes + 127) / 128;
    const int a_tiles  = (n_nodes + 3) / 4;

    cudaFuncSetAttribute(proj_kernel, cudaFuncAttributeMaxDynamicSharedMemorySize, PP_SMEM);
    cudaFuncSetAttribute(agg_kernel,  cudaFuncAttributeMaxDynamicSharedMemorySize, AG_SMEM);

    proj_kernel<<<296, 256, PP_SMEM>>>(V, nodes, W1, b1, n_videos, n_nodes, p_tiles, q_tiles);
    agg_kernel<<<296, 256, AG_SMEM>>>(neigh, W2, b2, W3, out, n_nodes, a_tiles);
}